// round 9
// baseline (speedup 1.0000x reference)
#include <cuda_runtime.h>
#include <cuda_bf16.h>
#include <math.h>

#define BB 16
#define SS 2048
#define DD 256
#define HM 256
#define PP 8
#define CHN 16
#define CC 128
#define LL 264            // PP + 2*CC
#define NH 8
#define HD 32
#define NSEG 16
#define PER (DD*HM + HM + HM*DD + DD)
#define LD_INV (1.0f/((float)LL*(float)DD))

// ---------------- persistent scratch (device globals; no allocation) -------
__device__ __align__(16) float g_fastW1[BB*DD*HM];
__device__ __align__(16) float g_fastb1[BB*HM];
__device__ __align__(16) float g_fastW2[BB*HM*DD];
__device__ __align__(16) float g_fastb2[BB*DD];
__device__ __align__(16) float g_momW1[BB*DD*HM];
__device__ __align__(16) float g_momb1[BB*HM];
__device__ __align__(16) float g_momW2[BB*HM*DD];
__device__ __align__(16) float g_momb2[BB*DD];
__device__ __align__(16) float g_gW1[BB*DD*HM];
__device__ __align__(16) float g_gb1[BB*HM];
__device__ __align__(16) float g_gW2[BB*HM*DD];
__device__ __align__(16) float g_gb2[BB*DD];
__device__ __align__(16) float g_qall[BB*SS*DD];
__device__ __align__(16) float g_Wkv[DD*2*DD];
__device__ __align__(16) float g_attn[BB*LL*DD];
__device__ __align__(16) float g_h1[BB*CC*HM];
__device__ __align__(16) float g_qkv[BB*LL*3*DD];
__device__ __align__(16) float g_ao[BB*LL*DD];
__device__ __align__(16) float g_y[BB*LL*DD];
__device__ __align__(16) float g_kv[BB*LL*2*DD];
__device__ __align__(16) float g_z[BB*LL*HM];
__device__ __align__(16) float g_s[BB*LL*HM];
__device__ __align__(16) float g_dz[BB*LL*HM];
__device__ __align__(16) float g_e[BB*LL*DD];
__device__ float g_coef[BB*3];

// ---------------- init: fast weights, momentum, Wkv concat, persistent -----
__global__ void k_init(const float* __restrict__ mW1, const float* __restrict__ mb1,
                       const float* __restrict__ mW2, const float* __restrict__ mb2,
                       const float* __restrict__ pers,
                       const float* __restrict__ W_K, const float* __restrict__ W_V) {
    long i = (long)blockIdx.x * blockDim.x + threadIdx.x;
    if (i < (long)BB*DD*HM) {
        g_fastW1[i] = mW1[i % (DD*HM)]; g_momW1[i] = 0.f;
        g_fastW2[i] = mW2[i % (HM*DD)]; g_momW2[i] = 0.f;
    }
    if (i < BB*HM) { g_fastb1[i] = mb1[i % HM]; g_momb1[i] = 0.f; }
    if (i < BB*DD) { g_fastb2[i] = mb2[i % DD]; g_momb2[i] = 0.f; }
    if (i < DD*2*DD) {
        int k = (int)(i >> 9), n = (int)(i & 511);
        g_Wkv[i] = (n < DD) ? W_K[k*DD + n] : W_V[k*DD + n - DD];
    }
    if (i < BB*PP*DD) {
        int d = (int)(i % DD); int t = (int)((i/DD) % PP); int b = (int)(i/(PP*DD));
        g_attn[((long)b*LL + t)*DD + d] = pers[t*DD + d];
    }
}

// ---------------- pack the x slice into attn_in rows [PP+CC, LL) -----------
__global__ void k_packx(const float* __restrict__ x, int s0) {
    int i = blockIdx.x * blockDim.x + threadIdx.x;
    if (i >= BB*CC*DD) return;
    int d = i % DD, t = (i/DD) % CC, b = i/(CC*DD);
    g_attn[((long)b*LL + PP + CC + t)*DD + d] = x[(size_t)b*SS*DD + (size_t)(s0+t)*DD + d];
}

// ---------------- bf16x3 helpers -------------------------------------------
__device__ __forceinline__ void split_bf(float x, __nv_bfloat16& h, __nv_bfloat16& l) {
    h = __float2bfloat16(x);
    l = __float2bfloat16(x - __bfloat162float(h));
}
__device__ __forceinline__ unsigned pack2(__nv_bfloat16 a, __nv_bfloat16 b) {
    __nv_bfloat162 t; t.x = a; t.y = b;
    return *(unsigned*)&t;
}
#define MMA_BF16(d, a, bq) \
    asm volatile("mma.sync.aligned.m16n8k16.row.col.f32.bf16.bf16.f32 " \
        "{%0,%1,%2,%3}, {%4,%5,%6,%7}, {%8,%9}, {%0,%1,%2,%3};" \
        : "+f"(d[0]), "+f"(d[1]), "+f"(d[2]), "+f"(d[3]) \
        : "r"(a[0]), "r"(a[1]), "r"(a[2]), "r"(a[3]), "r"(bq[0]), "r"(bq[1]))

// ---------------- tensor-core GEMM (bf16x3 = fp32-accurate) ----------------
// C = op(A) @ op(B) [+ bias] [+ epilogue], 64x64 tile, 4 warps, dbl-buffered.
// TA: A is [K][M] (elem (k,m) at A[k*lda+m]); else [M][K].   (TA => M%64==0)
// TB: B is [N][K]; else [K][N].                               (TB => K%16==0)
// EPI: 0 none | 1 silu | 2 C=z, C2=silu(z) | 3 (v-X1)*LD_INV | 4 acc*silu'(X1) | 5 v*X1
template<bool TA, bool TB, bool BIAS, int EPI>
__global__ void t_gemm(const float* __restrict__ A, const float* __restrict__ Bw,
                       const float* __restrict__ bias, float* __restrict__ C,
                       const float* __restrict__ X1, float* __restrict__ C2,
                       int M, int N, int K, int lda, int ldb, int ldc, int ldx1,
                       long sA, long sB, long sC, int sBias, long sX1) {
    __shared__ __align__(16) __nv_bfloat16 As[2][64][56];
    __shared__ __align__(16) __nv_bfloat16 Bs[2][64][56];
    int b = blockIdx.z;
    A  += (long)b * sA;
    Bw += (long)b * sB;
    C  += (long)b * sC;
    if (BIAS) bias += (long)b * sBias;
    if (EPI >= 3) X1 += (long)b * sX1;
    if (EPI == 2) C2 += (long)b * sC;
    int tid = threadIdx.x;
    int n0 = blockIdx.x * 64, m0 = blockIdx.y * 64;
    int nkt = (K + 15) >> 4;

    float ar[8], br[8];

    // staging index precompute
    int am  = tid >> 1, ak  = (tid & 1) * 8;        // !TA: A row, k-offset
    int ap  = tid >> 3, amq = (tid & 7) * 8;        //  TA: k-row, m-offset
    int bp  = tid >> 3, bn  = (tid & 7) * 8;        // !TB
    int bn2 = tid >> 1, bk  = (tid & 1) * 8;        //  TB

    const float* Aptr;
    if (!TA) { int r = m0 + am; if (r >= M) r = M - 1; Aptr = A + (long)r*lda + ak; }

    // ---- read tile kt into regs ----
    auto readA = [&](int kt) {
        if (!TA) {
            float4 a0 = *(const float4*)(Aptr + kt*16);
            float4 a1 = *(const float4*)(Aptr + kt*16 + 4);
            ar[0]=a0.x; ar[1]=a0.y; ar[2]=a0.z; ar[3]=a0.w;
            ar[4]=a1.x; ar[5]=a1.y; ar[6]=a1.z; ar[7]=a1.w;
        } else {
            int kr = kt*16 + ap;
            if (kr < K) {
                const float* p = A + (long)kr*lda + m0 + amq;
                float4 a0 = *(const float4*)p;
                float4 a1 = *(const float4*)(p + 4);
                ar[0]=a0.x; ar[1]=a0.y; ar[2]=a0.z; ar[3]=a0.w;
                ar[4]=a1.x; ar[5]=a1.y; ar[6]=a1.z; ar[7]=a1.w;
            } else {
                #pragma unroll
                for (int j = 0; j < 8; j++) ar[j] = 0.f;
            }
        }
    };
    auto readB = [&](int kt) {
        if (!TB) {
            int kr = kt*16 + bp;
            if (kr < K) {
                const float* p = Bw + (long)kr*ldb + n0 + bn;
                float4 b0 = *(const float4*)p;
                float4 b1 = *(const float4*)(p + 4);
                br[0]=b0.x; br[1]=b0.y; br[2]=b0.z; br[3]=b0.w;
                br[4]=b1.x; br[5]=b1.y; br[6]=b1.z; br[7]=b1.w;
            } else {
                #pragma unroll
                for (int j = 0; j < 8; j++) br[j] = 0.f;
            }
        } else {
            const float* p = Bw + (long)(n0 + bn2)*ldb + kt*16 + bk;
            float4 b0 = *(const float4*)p;
            float4 b1 = *(const float4*)(p + 4);
            br[0]=b0.x; br[1]=b0.y; br[2]=b0.z; br[3]=b0.w;
            br[4]=b1.x; br[5]=b1.y; br[6]=b1.z; br[7]=b1.w;
        }
    };
    // ---- split + store regs into smem buffer ----
    // A layout over k' (48): hi at [p], lo at [16+p], hi at [32+p]
    // B layout over k' (48): hi at [p], hi at [16+p], lo at [32+p]
    auto storeA = [&](int buf) {
        __nv_bfloat16 h[8], l[8];
        #pragma unroll
        for (int j = 0; j < 8; j++) split_bf(ar[j], h[j], l[j]);
        if (!TA) {
            #pragma unroll
            for (int j = 0; j < 8; j += 2) {
                unsigned ph = pack2(h[j], h[j+1]);
                unsigned pl = pack2(l[j], l[j+1]);
                *(unsigned*)&As[buf][am][ak+j]      = ph;
                *(unsigned*)&As[buf][am][ak+j+32]   = ph;
                *(unsigned*)&As[buf][am][ak+j+16]   = pl;
            }
        } else {
            #pragma unroll
            for (int j = 0; j < 8; j++) {
                As[buf][amq+j][ap]      = h[j];
                As[buf][amq+j][ap+32]   = h[j];
                As[buf][amq+j][ap+16]   = l[j];
            }
        }
    };
    auto storeB = [&](int buf) {
        __nv_bfloat16 h[8], l[8];
        #pragma unroll
        for (int j = 0; j < 8; j++) split_bf(br[j], h[j], l[j]);
        if (!TB) {
            #pragma unroll
            for (int j = 0; j < 8; j++) {
                Bs[buf][bn+j][bp]      = h[j];
                Bs[buf][bn+j][bp+16]   = h[j];
                Bs[buf][bn+j][bp+32]   = l[j];
            }
        } else {
            #pragma unroll
            for (int j = 0; j < 8; j += 2) {
                unsigned ph = pack2(h[j], h[j+1]);
                unsigned pl = pack2(l[j], l[j+1]);
                *(unsigned*)&Bs[buf][bn2][bk+j]      = ph;
                *(unsigned*)&Bs[buf][bn2][bk+j+16]   = ph;
                *(unsigned*)&Bs[buf][bn2][bk+j+32]   = pl;
            }
        }
    };

    int warp = tid >> 5, lane = tid & 31;
    int wm = warp & 1, wn = warp >> 1;
    int g = lane >> 2, tq = lane & 3;
    float acc[2][4][4] = {};

    readA(0); readB(0);
    storeA(0); storeB(0);
    __syncthreads();

    for (int kt = 0; kt < nkt; kt++) {
        int cur = kt & 1;
        if (kt + 1 < nkt) { readA(kt+1); readB(kt+1); }
        #pragma unroll
        for (int ks = 0; ks < 3; ks++) {
            int ko = ks*16 + tq*2;
            unsigned a[2][4], bq[4][2];
            #pragma unroll
            for (int mi = 0; mi < 2; mi++) {
                int r = wm*32 + mi*16 + g;
                a[mi][0] = *(const unsigned*)&As[cur][r][ko];
                a[mi][1] = *(const unsigned*)&As[cur][r+8][ko];
                a[mi][2] = *(const unsigned*)&As[cur][r][ko+8];
                a[mi][3] = *(const unsigned*)&As[cur][r+8][ko+8];
            }
            #pragma unroll
            for (int ni = 0; ni < 4; ni++) {
                int nr = wn*32 + ni*8 + g;
                bq[ni][0] = *(const unsigned*)&Bs[cur][nr][ko];
                bq[ni][1] = *(const unsigned*)&Bs[cur][nr][ko+8];
            }
            #pragma unroll
            for (int mi = 0; mi < 2; mi++)
                #pragma unroll
                for (int ni = 0; ni < 4; ni++)
                    MMA_BF16(acc[mi][ni], a[mi], bq[ni]);
        }
        if (kt + 1 < nkt) { storeA(cur ^ 1); storeB(cur ^ 1); }
        __syncthreads();
    }

    // ---- epilogue ----
    #pragma unroll
    for (int mi = 0; mi < 2; mi++) {
        #pragma unroll
        for (int ni = 0; ni < 4; ni++) {
            int c0 = n0 + wn*32 + ni*8 + tq*2;
            float bv0 = 0.f, bv1 = 0.f;
            if (BIAS) { bv0 = bias[c0]; bv1 = bias[c0+1]; }
            #pragma unroll
            for (int hh = 0; hh < 2; hh++) {
                int r = m0 + wm*32 + mi*16 + g + hh*8;
                if (r < M) {
                    float v0 = acc[mi][ni][hh*2+0] + bv0;
                    float v1 = acc[mi][ni][hh*2+1] + bv1;
                    if (EPI == 1) {
                        v0 = v0 / (1.f + expf(-v0));
                        v1 = v1 / (1.f + expf(-v1));
                    } else if (EPI == 2) {
                        C2[(long)r*ldc + c0]   = v0 / (1.f + expf(-v0));
                        C2[(long)r*ldc + c0+1] = v1 / (1.f + expf(-v1));
                    } else if (EPI == 3) {
                        v0 = (v0 - X1[(long)r*ldx1 + c0])   * LD_INV;
                        v1 = (v1 - X1[(long)r*ldx1 + c0+1]) * LD_INV;
                    } else if (EPI == 4) {
                        float z0 = X1[(long)r*ldx1 + c0];
                        float z1 = X1[(long)r*ldx1 + c0+1];
                        float s0_ = 1.f/(1.f+expf(-z0)), s1_ = 1.f/(1.f+expf(-z1));
                        v0 *= s0_ * (1.f + z0*(1.f - s0_));
                        v1 *= s1_ * (1.f + z1*(1.f - s1_));
                    } else if (EPI == 5) {
                        v0 *= X1[(long)r*ldx1 + c0];
                        v1 *= X1[(long)r*ldx1 + c0+1];
                    }
                    C[(long)r*ldc + c0]   = v0;
                    C[(long)r*ldc + c0+1] = v1;
                }
            }
        }
    }
}

// ---------------- attention: block = (b, head, 8-row tile), smem K/V -------
__global__ void k_attn2() {
    __shared__ float Ks[64][33];
    __shared__ float Vs[64][33];
    __shared__ float qs[8][32];
    __shared__ float ps[8][32];
    int blk = blockIdx.x;
    int tile = blk % (LL/8);
    int hh = (blk / (LL/8)) % NH;
    int b  = blk / ((LL/8)*NH);
    int rt0 = tile * 8;
    int tid = threadIdx.x;
    int w = tid >> 5, lane = tid & 31;
    int r = rt0 + w;
    const float* base = g_qkv + (long)b*LL*3*DD;
    qs[w][lane] = base[(long)r*3*DD + hh*HD + lane] * 0.17677669529663687f;
    float m = -1e30f, l = 0.f, o = 0.f;
    int ntile = (rt0 + 71) >> 6;
    int krow = tid >> 3;
    int kc = (tid & 7) * 4;
    for (int jt = 0; jt < ntile; jt++) {
        int j0 = jt * 64;
        __syncthreads();
        #pragma unroll
        for (int half = 0; half < 2; half++) {
            int jl = krow + half*32;
            int jg = j0 + jl; if (jg > LL-1) jg = LL-1;
            const float* kp = base + (long)jg*3*DD + DD + hh*HD + kc;
            float4 k4 = *(const float4*)kp;
            float4 v4 = *(const float4*)(kp + DD);
            Ks[jl][kc]=k4.x; Ks[jl][kc+1]=k4.y; Ks[jl][kc+2]=k4.z; Ks[jl][kc+3]=k4.w;
            Vs[jl][kc]=v4.x; Vs[jl][kc+1]=v4.y; Vs[jl][kc+2]=v4.z; Vs[jl][kc+3]=v4.w;
        }
        __syncthreads();
        #pragma unroll
        for (int c = 0; c < 2; c++) {
            int jbase = j0 + c*32;
            if (jbase > r) break;
            int jl = c*32 + lane;
            int jg = jbase + lane;
            float sc = 0.f;
            #pragma unroll
            for (int d = 0; d < 32; d++) sc += qs[w][d] * Ks[jl][d];
            if (jg > r) sc = -1e30f;
            float cm = sc;
            #pragma unroll
            for (int s = 16; s; s >>= 1) cm = fmaxf(cm, __shfl_xor_sync(0xffffffffu, cm, s));
            float mn = fmaxf(m, cm);
            float p = (jg <= r) ? expf(sc - mn) : 0.f;
            __syncwarp();
            ps[w][lane] = p;
            float psum = p;
            #pragma unroll
            for (int s = 16; s; s >>= 1) psum += __shfl_xor_sync(0xffffffffu, psum, s);
            float corr = expf(m - mn);
            l = l*corr + psum; o *= corr; m = mn;
            __syncwarp();
            int jmax = min(32, r - jbase + 1);
            for (int jj = 0; jj < jmax; jj++)
                o += ps[w][jj] * Vs[c*32 + jj][lane];
        }
    }
    g_ao[((long)b*LL + r)*DD + hh*HD + lane] = o / l;
}

// ---------------- bias grads: gb2 = colsum(e), gb1 = colsum(dz) ------------
__global__ void k_gbias() {
    int b = blockIdx.x, tid = threadIdx.x;
    if (blockIdx.y == 0) {
        const float* p = g_e + (long)b*LL*DD + tid;
        float s = 0.f;
        for (int t = 0; t < LL; t++) s += p[(long)t*DD];
        g_gb2[b*DD + tid] = s;
    } else {
        const float* p = g_dz + (long)b*LL*HM + tid;
        float s = 0.f;
        for (int t = 0; t < LL; t++) s += p[(long)t*HM];
        g_gb1[b*HM + tid] = s;
    }
}

// ---------------- gate coefficients ----------------------------------------
__global__ void k_coef(const float* __restrict__ cW1, const float* __restrict__ cb1,
                       const float* __restrict__ cW2, const float* __restrict__ cb2) {
    int b = blockIdx.x, tid = threadIdx.x;
    __shared__ float ybar[DD];
    __shared__ float ch[CHN];
    float sum = 0.f;
    const float* yp = g_y + (long)b*LL*DD + tid;
    for (int t = 0; t < LL; t++) sum += yp[(long)t*DD];
    ybar[tid] = sum / (float)LL;
    __syncthreads();
    if (tid < CHN) {
        float a = cb1[tid];
        for (int d = 0; d < DD; d++) a += ybar[d] * cW1[d*CHN + tid];
        ch[tid] = a / (1.f + expf(-a));
    }
    __syncthreads();
    if (tid < 3) {
        float a = cb2[tid];
        for (int j = 0; j < CHN; j++) a += ch[j] * cW2[j*3 + tid];
        g_coef[b*3 + tid] = 1.f / (1.f + expf(-a));
    }
}

// ---------------- momentum + decay update ----------------------------------
__global__ void k_update() {
    long i = (long)blockIdx.x * blockDim.x + threadIdx.x;
    if (i >= (long)BB*PER) return;
    int b = (int)(i / PER), off = (int)(i % PER);
    float alpha = g_coef[b*3+0], eta = g_coef[b*3+1], theta = g_coef[b*3+2];
    float *fp, *mp, *gp;
    long idx;
    if (off < DD*HM)                   { fp = g_fastW1; mp = g_momW1; gp = g_gW1; idx = (long)b*DD*HM + off; }
    else if (off < DD*HM + HM)         { int o = off - DD*HM; fp = g_fastb1; mp = g_momb1; gp = g_gb1; idx = b*HM + o; }
    else if (off < DD*HM + HM + HM*DD) { int o = off - DD*HM - HM; fp = g_fastW2; mp = g_momW2; gp = g_gW2; idx = (long)b*HM*DD + o; }
    else                               { int o = off - DD*HM - HM - HM*DD; fp = g_fastb2; mp = g_momb2; gp = g_gb2; idx = b*DD + o; }
    float m = eta * mp[idx] - theta * gp[idx];
    mp[idx] = m;
    fp[idx] = (1.f - alpha) * fp[idx] + m;
}

// ---------------------------------------------------------------------------
extern "C" void kernel_launch(void* const* d_in, const int* in_sizes, int n_in,
                              void* d_out, int out_size) {
    const float* x     = (const float*)d_in[0];
    const float* pers  = (const float*)d_in[1];
    const float* W_Q   = (const float*)d_in[2];
    const float* in_w  = (const float*)d_in[3];
    const float* in_b  = (const float*)d_in[4];
    const float* out_w = (const float*)d_in[5];
    const float* out_b = (const float*)d_in[6];
    const float* mW1   = (const float*)d_in[7];
    const float* mb1   = (const float*)d_in[8];
    const float* mW2   = (const float*)d_in[9];
    const float* mb2   = (const float*)d_in[10];
    const float* W_K   = (const float*)d_in[11];
    const float* W_V   = (const float*)d_in[12];
    const float* cW1   = (const float*)d_in[13];
    const float* cb1   = (const float*)d_in[14];
    const float* cW2   = (const float*)d_in[15];
    const float* cb2   = (const float*)d_in[16];
    float* out = (float*)d_out;

    float *fW1, *fb1, *fW2, *fb2, *pQall, *pWkv, *pAttn, *pH1, *pQkv, *pAo, *pY;
    float *pKV, *pZ, *pS, *pDz, *pE, *pGW1, *pGW2;
    cudaGetSymbolAddress((void**)&fW1, g_fastW1);
    cudaGetSymbolAddress((void**)&fb1, g_fastb1);
    cudaGetSymbolAddress((void**)&fW2, g_fastW2);
    cudaGetSymbolAddress((void**)&fb2, g_fastb2);
    cudaGetSymbolAddress((void**)&pQall, g_qall);
    cudaGetSymbolAddress((void**)&pWkv, g_Wkv);
    cudaGetSymbolAddress((void**)&pAttn, g_attn);
    cudaGetSymbolAddress((void**)&pH1, g_h1);
    cudaGetSymbolAddress((void**)&pQkv, g_qkv);
    cudaGetSymbolAddress((void**)&pAo, g_ao);
    cudaGetSymbolAddress((void**)&pY, g_y);
    cudaGetSymbolAddress((void**)&pKV, g_kv);
    cudaGetSymbolAddress((void**)&pZ, g_z);
    cudaGetSymbolAddress((void**)&pS, g_s);
    cudaGetSymbolAddress((void**)&pDz, g_dz);
    cudaGetSymbolAddress((void**)&pE, g_e);
    cudaGetSymbolAddress((void**)&pGW1, g_gW1);
    cudaGetSymbolAddress((void**)&pGW2, g_gW2);

    k_init<<<((long)BB*DD*HM + 255)/256, 256>>>(mW1, mb1, mW2, mb2, pers, W_K, W_V);

    // Q_all = x @ W_Q  (M = 32768)
    t_gemm<false,false,false,0><<<dim3(DD/64, (BB*SS)/64, 1), 128>>>(
        x, W_Q, nullptr, pQall, nullptr, nullptr,
        BB*SS, DD, DD, DD, DD, DD, 0, 0L, 0L, 0L, 0, 0L);

    for (int s = 0; s < NSEG; s++) {
        int s0 = s * CC;
        k_packx<<<(BB*CC*DD + 255)/256, 256>>>(x, s0);

        // h1 = silu(q_seg @ fastW1 + fastb1)
        t_gemm<false,false,true,1><<<dim3(HM/64, CC/64, BB), 128>>>(
            pQall + (long)s0*DD, fW1, fb1, pH1, nullptr, nullptr,
            CC, HM, DD, DD, HM, HM, 0, (long)SS*DD, (long)DD*HM, (long)CC*HM, HM, 0L);
        // h = h1 @ fastW2 + fastb2 -> attn_in rows [PP, PP+CC)
        t_gemm<false,false,true,0><<<dim3(DD/64, CC/64, BB), 128>>>(
            pH1, fW2, fb2, pAttn + PP*DD, nullptr, nullptr,
            CC, DD, HM, HM, DD, DD, 0, (long)CC*HM, (long)HM*DD, (long)LL*DD, DD, 0L);

        // qkv = attn_in @ in_proj_w^T + in_proj_b  (M = 4224)
        t_gemm<false,true,true,0><<<dim3((3*DD)/64, (BB*LL)/64, 1), 128>>>(
            pAttn, in_w, in_b, pQkv, nullptr, nullptr,
            BB*LL, 3*DD, DD, DD, DD, 3*DD, 0, 0L, 0L, 0L, 0, 0L);
        k_attn2<<<BB*NH*(LL/8), 256>>>();
        // y = ao @ out_proj_w^T + out_proj_b
        t_gemm<false,true,true,0><<<dim3(DD/64, (BB*LL)/64, 1), 128>>>(
            pAo, out_w, out_b, pY, nullptr, nullptr,
            BB*LL, DD, DD, DD, DD, DD, 0, 0L, 0L, 0L, 0, 0L);
        // [k|v] = y @ Wkv
        t_gemm<false,false,false,0><<<dim3((2*DD)/64, (BB*LL)/64, 1), 128>>>(
            pY, pWkv, nullptr, pKV, nullptr, nullptr,
            BB*LL, 2*DD, DD, DD, 2*DD, 2*DD, 0, 0L, 0L, 0L, 0, 0L);

        // z = k @ W1 + b1 ; s = silu(z)
        t_gemm<false,false,true,2><<<dim3(HM/64, (LL+63)/64, BB), 128>>>(
            pKV, fW1, fb1, pZ, nullptr, pS,
            LL, HM, DD, 2*DD, HM, HM, 0, (long)LL*2*DD, (long)DD*HM, (long)LL*HM, HM, 0L);
        // e = (s @ W2 + b2 - v) * LD_INV
        t_gemm<false,false,true,3><<<dim3(DD/64, (LL+63)/64, BB), 128>>>(
            pS, fW2, fb2, pE, pKV + DD, nullptr,
            LL, DD, HM, HM, DD, DD, 2*DD, (long)LL*HM, (long)HM*DD, (long)LL*DD, DD, (long)LL*2*DD);
        // dz = (e @ W2^T) * silu'(z)
        t_gemm<false,true,false,4><<<dim3(HM/64, (LL+63)/64, BB), 128>>>(
            pE, fW2, nullptr, pDz, pZ, nullptr,
            LL, HM, DD, DD, DD, HM, HM, (long)LL*DD, (long)HM*DD, (long)LL*HM, 0, (long)LL*HM);
        // gW2[h,d] = sum_t s[t,h] e[t,d]
        t_gemm<true,false,false,0><<<dim3(DD/64, HM/64, BB), 128>>>(
            pS, pE, nullptr, pGW2, nullptr, nullptr,
            HM, DD, LL, HM, DD, DD, 0, (long)LL*HM, (long)LL*DD, (long)HM*DD, 0, 0L);
        // gW1[d,h] = sum_t k[t,d] dz[t,h]
        t_gemm<true,false,false,0><<<dim3(HM/64, DD/64, BB), 128>>>(
            pKV, pDz, nullptr, pGW1, nullptr, nullptr,
            DD, HM, LL, 2*DD, HM, HM, 0, (long)LL*2*DD, (long)LL*HM, (long)DD*HM, 0, 0L);
        k_gbias<<<dim3(BB, 2), 256>>>();

        k_coef<<<BB, 256>>>(cW1, cb1, cW2, cb2);
        k_update<<<((long)BB*PER + 255)/256, 256>>>();

        // final: mem_apply(updated weights, y_last) gated by y_last -> out
        t_gemm<false,false,true,1><<<dim3(HM/64, CC/64, BB), 128>>>(
            pY + (long)(PP+CC)*DD, fW1, fb1, pH1, nullptr, nullptr,
            CC, HM, DD, DD, HM, HM, 0, (long)LL*DD, (long)DD*HM, (long)CC*HM, HM, 0L);
        t_gemm<false,false,true,5><<<dim3(DD/64, CC/64, BB), 128>>>(
            pH1, fW2, fb2, out + (long)s0*DD, pY + (long)(PP+CC)*DD, nullptr,
            CC, DD, HM, HM, DD, DD, DD, (long)CC*HM, (long)HM*DD, (long)SS*DD, DD, (long)LL*DD);
    }
}

// round 10
// speedup vs baseline: 1.2549x; 1.2549x over previous
#include <cuda_runtime.h>
#include <cuda_bf16.h>
#include <math.h>

#define BB 16
#define SS 2048
#define DD 256
#define HM 256
#define PP 8
#define CHN 16
#define CC 128
#define LL 264            // PP + 2*CC
#define NH 8
#define HD 32
#define NSEG 16
#define PER (DD*HM + HM + HM*DD + DD)
#define LD_INV (1.0f/((float)LL*(float)DD))

// ---------------- persistent scratch (device globals; no allocation) -------
__device__ __align__(16) float g_fastW1[BB*DD*HM];
__device__ __align__(16) float g_fastb1[BB*HM];
__device__ __align__(16) float g_fastW2[BB*HM*DD];
__device__ __align__(16) float g_fastb2[BB*DD];
__device__ __align__(16) float g_momW1[BB*DD*HM];
__device__ __align__(16) float g_momb1[BB*HM];
__device__ __align__(16) float g_momW2[BB*HM*DD];
__device__ __align__(16) float g_momb2[BB*DD];
__device__ __align__(16) float g_gW1[BB*DD*HM];
__device__ __align__(16) float g_gb1[BB*HM];
__device__ __align__(16) float g_gW2[BB*HM*DD];
__device__ __align__(16) float g_gb2[BB*DD];
__device__ __align__(16) float g_qall[BB*SS*DD];
__device__ __align__(16) float g_Wkv[DD*2*DD];
__device__ __align__(16) float g_attn[BB*LL*DD];
__device__ __align__(16) float g_h1[BB*CC*HM];
__device__ __align__(16) float g_qkv[BB*LL*3*DD];
__device__ __align__(16) float g_ao[BB*LL*DD];
__device__ __align__(16) float g_y[BB*LL*DD];
__device__ __align__(16) float g_kv[BB*LL*2*DD];
__device__ __align__(16) float g_z[BB*LL*HM];
__device__ __align__(16) float g_s[BB*LL*HM];
__device__ __align__(16) float g_dz[BB*LL*HM];
__device__ __align__(16) float g_e[BB*LL*DD];
__device__ float g_coef[BB*3];

// ---------------- init: fast weights, momentum, Wkv concat, persistent -----
__global__ void k_init(const float* __restrict__ mW1, const float* __restrict__ mb1,
                       const float* __restrict__ mW2, const float* __restrict__ mb2,
                       const float* __restrict__ pers,
                       const float* __restrict__ W_K, const float* __restrict__ W_V) {
    long i = (long)blockIdx.x * blockDim.x + threadIdx.x;
    if (i < (long)BB*DD*HM) {
        g_fastW1[i] = mW1[i % (DD*HM)]; g_momW1[i] = 0.f;
        g_fastW2[i] = mW2[i % (HM*DD)]; g_momW2[i] = 0.f;
    }
    if (i < BB*HM) { g_fastb1[i] = mb1[i % HM]; g_momb1[i] = 0.f; }
    if (i < BB*DD) { g_fastb2[i] = mb2[i % DD]; g_momb2[i] = 0.f; }
    if (i < DD*2*DD) {
        int k = (int)(i >> 9), n = (int)(i & 511);
        g_Wkv[i] = (n < DD) ? W_K[k*DD + n] : W_V[k*DD + n - DD];
    }
    if (i < BB*PP*DD) {
        int d = (int)(i % DD); int t = (int)((i/DD) % PP); int b = (int)(i/(PP*DD));
        g_attn[((long)b*LL + t)*DD + d] = pers[t*DD + d];
    }
}

// ---------------- pack the x slice into attn_in rows [PP+CC, LL) -----------
__global__ void k_packx(const float* __restrict__ x, int s0) {
    int i = blockIdx.x * blockDim.x + threadIdx.x;
    if (i >= BB*CC*DD) return;
    int d = i % DD, t = (i/DD) % CC, b = i/(CC*DD);
    g_attn[((long)b*LL + PP + CC + t)*DD + d] = x[(size_t)b*SS*DD + (size_t)(s0+t)*DD + d];
}

// ---------------- bf16 split helpers (truncation hi + rn lo) ---------------
__device__ __forceinline__ void split2(float x0, float x1, unsigned& ph, unsigned& pl) {
    unsigned b0 = __float_as_uint(x0), b1 = __float_as_uint(x1);
    ph = __byte_perm(b0, b1, 0x7632);                    // (hi16(x1)<<16)|hi16(x0)
    float l0 = x0 - __uint_as_float(b0 & 0xFFFF0000u);
    float l1 = x1 - __uint_as_float(b1 & 0xFFFF0000u);
    __nv_bfloat162 t = __float22bfloat162_rn(make_float2(l0, l1));
    pl = *(unsigned*)&t;
}
__device__ __forceinline__ void split1(float x, __nv_bfloat16& h, __nv_bfloat16& l) {
    unsigned b = __float_as_uint(x);
    unsigned short hs = (unsigned short)(b >> 16);
    h = *reinterpret_cast<__nv_bfloat16*>(&hs);
    l = __float2bfloat16(x - __uint_as_float(b & 0xFFFF0000u));
}
#define MMA_BF16(d, a, bq) \
    asm volatile("mma.sync.aligned.m16n8k16.row.col.f32.bf16.bf16.f32 " \
        "{%0,%1,%2,%3}, {%4,%5,%6,%7}, {%8,%9}, {%0,%1,%2,%3};" \
        : "+f"(d[0]), "+f"(d[1]), "+f"(d[2]), "+f"(d[3]) \
        : "r"(a[0]), "r"(a[1]), "r"(a[2]), "r"(a[3]), "r"(bq[0]), "r"(bq[1]))

#define KP 24   // smem row pitch in bf16 elems (16 data + 8 pad)

// ---------------- tensor-core GEMM (bf16x3 = fp32-accurate) ----------------
// 64x64 tile, 256 threads (8 warps, 2m x 4n, warp tile 32x16), dbl-buffered.
// TA: A is [K][M]; else [M][K].  (TA => M%64==0)
// TB: B is [N][K]; else [K][N].
// EPI: 0 none | 1 silu | 2 C=z,C2=silu(z) | 3 (v-X1)*LD_INV | 4 acc*silu'(X1) | 5 v*X1
template<bool TA, bool TB, bool BIAS, int EPI>
__global__ __launch_bounds__(256) void t_gemm(
        const float* __restrict__ A, const float* __restrict__ Bw,
        const float* __restrict__ bias, float* __restrict__ C,
        const float* __restrict__ X1, float* __restrict__ C2,
        int M, int N, int K, int lda, int ldb, int ldc, int ldx1,
        long sA, long sB, long sC, int sBias, long sX1) {
    __shared__ __align__(16) __nv_bfloat16 AsH[2][64][KP];
    __shared__ __align__(16) __nv_bfloat16 AsL[2][64][KP];
    __shared__ __align__(16) __nv_bfloat16 BsH[2][64][KP];
    __shared__ __align__(16) __nv_bfloat16 BsL[2][64][KP];
    int b = blockIdx.z;
    A  += (long)b * sA;
    Bw += (long)b * sB;
    C  += (long)b * sC;
    if (BIAS) bias += (long)b * sBias;
    if (EPI >= 3) X1 += (long)b * sX1;
    if (EPI == 2) C2 += (long)b * sC;
    int tid = threadIdx.x;
    int n0 = blockIdx.x * 64, m0 = blockIdx.y * 64;
    int nkt = (K + 15) >> 4;

    float ar[4], br[4];

    // staging indices
    int am  = tid >> 2, akq = (tid & 3) * 4;     // !TA: A row 0..63, k 0..12
    int akr = tid >> 4, amq = (tid & 15) * 4;    //  TA: k-row 0..15, m 0..60
    int bkr = tid >> 4, bnq = (tid & 15) * 4;    // !TB
    int bn  = tid >> 2, bkq = (tid & 3) * 4;     //  TB

    const float* Aptr;
    if (!TA) { int r = m0 + am; if (r >= M) r = M - 1; Aptr = A + (long)r*lda; }

    auto readA = [&](int kt) {
        if (!TA) {
            float4 v = *(const float4*)(Aptr + kt*16 + akq);
            ar[0]=v.x; ar[1]=v.y; ar[2]=v.z; ar[3]=v.w;
        } else {
            int kr = kt*16 + akr;
            if (kr < K) {
                float4 v = *(const float4*)(A + (long)kr*lda + m0 + amq);
                ar[0]=v.x; ar[1]=v.y; ar[2]=v.z; ar[3]=v.w;
            } else { ar[0]=ar[1]=ar[2]=ar[3]=0.f; }
        }
    };
    auto readB = [&](int kt) {
        if (!TB) {
            int kr = kt*16 + bkr;
            if (kr < K) {
                float4 v = *(const float4*)(Bw + (long)kr*ldb + n0 + bnq);
                br[0]=v.x; br[1]=v.y; br[2]=v.z; br[3]=v.w;
            } else { br[0]=br[1]=br[2]=br[3]=0.f; }
        } else {
            float4 v = *(const float4*)(Bw + (long)(n0+bn)*ldb + kt*16 + bkq);
            br[0]=v.x; br[1]=v.y; br[2]=v.z; br[3]=v.w;
        }
    };
    auto storeA = [&](int buf) {
        if (!TA) {
            unsigned ph0, pl0, ph1, pl1;
            split2(ar[0], ar[1], ph0, pl0);
            split2(ar[2], ar[3], ph1, pl1);
            *(unsigned*)&AsH[buf][am][akq]   = ph0;
            *(unsigned*)&AsH[buf][am][akq+2] = ph1;
            *(unsigned*)&AsL[buf][am][akq]   = pl0;
            *(unsigned*)&AsL[buf][am][akq+2] = pl1;
        } else {
            #pragma unroll
            for (int j = 0; j < 4; j++) {
                __nv_bfloat16 h, l;
                split1(ar[j], h, l);
                AsH[buf][amq+j][akr] = h;
                AsL[buf][amq+j][akr] = l;
            }
        }
    };
    auto storeB = [&](int buf) {
        if (!TB) {
            #pragma unroll
            for (int j = 0; j < 4; j++) {
                __nv_bfloat16 h, l;
                split1(br[j], h, l);
                BsH[buf][bnq+j][bkr] = h;
                BsL[buf][bnq+j][bkr] = l;
            }
        } else {
            unsigned ph0, pl0, ph1, pl1;
            split2(br[0], br[1], ph0, pl0);
            split2(br[2], br[3], ph1, pl1);
            *(unsigned*)&BsH[buf][bn][bkq]   = ph0;
            *(unsigned*)&BsH[buf][bn][bkq+2] = ph1;
            *(unsigned*)&BsL[buf][bn][bkq]   = pl0;
            *(unsigned*)&BsL[buf][bn][bkq+2] = pl1;
        }
    };

    int warp = tid >> 5, lane = tid & 31;
    int wm = warp & 1, wn = warp >> 1;           // wm 0..1 (32 rows), wn 0..3 (16 cols)
    int g = lane >> 2, tq = lane & 3;
    int ko = tq * 2;
    float acc[2][2][4] = {};

    readA(0); readB(0);
    storeA(0); storeB(0);
    __syncthreads();

    for (int kt = 0; kt < nkt; kt++) {
        int cur = kt & 1;
        if (kt + 1 < nkt) { readA(kt+1); readB(kt+1); }
        unsigned ah[2][4], al[2][4], bh[2][2], bl[2][2];
        #pragma unroll
        for (int mi = 0; mi < 2; mi++) {
            int r = wm*32 + mi*16 + g;
            ah[mi][0] = *(const unsigned*)&AsH[cur][r][ko];
            ah[mi][1] = *(const unsigned*)&AsH[cur][r+8][ko];
            ah[mi][2] = *(const unsigned*)&AsH[cur][r][ko+8];
            ah[mi][3] = *(const unsigned*)&AsH[cur][r+8][ko+8];
            al[mi][0] = *(const unsigned*)&AsL[cur][r][ko];
            al[mi][1] = *(const unsigned*)&AsL[cur][r+8][ko];
            al[mi][2] = *(const unsigned*)&AsL[cur][r][ko+8];
            al[mi][3] = *(const unsigned*)&AsL[cur][r+8][ko+8];
        }
        #pragma unroll
        for (int ni = 0; ni < 2; ni++) {
            int nr = wn*16 + ni*8 + g;
            bh[ni][0] = *(const unsigned*)&BsH[cur][nr][ko];
            bh[ni][1] = *(const unsigned*)&BsH[cur][nr][ko+8];
            bl[ni][0] = *(const unsigned*)&BsL[cur][nr][ko];
            bl[ni][1] = *(const unsigned*)&BsL[cur][nr][ko+8];
        }
        #pragma unroll
        for (int mi = 0; mi < 2; mi++)
            #pragma unroll
            for (int ni = 0; ni < 2; ni++) {
                MMA_BF16(acc[mi][ni], ah[mi], bh[ni]);
                MMA_BF16(acc[mi][ni], al[mi], bh[ni]);
                MMA_BF16(acc[mi][ni], ah[mi], bl[ni]);
            }
        if (kt + 1 < nkt) { storeA(cur ^ 1); storeB(cur ^ 1); }
        __syncthreads();
    }

    // ---- epilogue ----
    #pragma unroll
    for (int mi = 0; mi < 2; mi++) {
        #pragma unroll
        for (int ni = 0; ni < 2; ni++) {
            int c0 = n0 + wn*16 + ni*8 + tq*2;
            float bv0 = 0.f, bv1 = 0.f;
            if (BIAS) { bv0 = bias[c0]; bv1 = bias[c0+1]; }
            #pragma unroll
            for (int hh = 0; hh < 2; hh++) {
                int r = m0 + wm*32 + mi*16 + g + hh*8;
                if (r < M) {
                    float v0 = acc[mi][ni][hh*2+0] + bv0;
                    float v1 = acc[mi][ni][hh*2+1] + bv1;
                    if (EPI == 1) {
                        v0 = v0 / (1.f + expf(-v0));
                        v1 = v1 / (1.f + expf(-v1));
                    } else if (EPI == 2) {
                        C2[(long)r*ldc + c0]   = v0 / (1.f + expf(-v0));
                        C2[(long)r*ldc + c0+1] = v1 / (1.f + expf(-v1));
                    } else if (EPI == 3) {
                        v0 = (v0 - X1[(long)r*ldx1 + c0])   * LD_INV;
                        v1 = (v1 - X1[(long)r*ldx1 + c0+1]) * LD_INV;
                    } else if (EPI == 4) {
                        float z0 = X1[(long)r*ldx1 + c0];
                        float z1 = X1[(long)r*ldx1 + c0+1];
                        float s0_ = 1.f/(1.f+expf(-z0)), s1_ = 1.f/(1.f+expf(-z1));
                        v0 *= s0_ * (1.f + z0*(1.f - s0_));
                        v1 *= s1_ * (1.f + z1*(1.f - s1_));
                    } else if (EPI == 5) {
                        v0 *= X1[(long)r*ldx1 + c0];
                        v1 *= X1[(long)r*ldx1 + c0+1];
                    }
                    C[(long)r*ldc + c0]   = v0;
                    C[(long)r*ldc + c0+1] = v1;
                }
            }
        }
    }
}

// ---------------- attention: block = (b, head, 8-row tile), smem K/V -------
__global__ void k_attn2() {
    __shared__ float Ks[64][33];
    __shared__ float Vs[64][33];
    __shared__ float qs[8][32];
    __shared__ float ps[8][32];
    int blk = blockIdx.x;
    int tile = blk % (LL/8);
    int hh = (blk / (LL/8)) % NH;
    int b  = blk / ((LL/8)*NH);
    int rt0 = tile * 8;
    int tid = threadIdx.x;
    int w = tid >> 5, lane = tid & 31;
    int r = rt0 + w;
    const float* base = g_qkv + (long)b*LL*3*DD;
    qs[w][lane] = base[(long)r*3*DD + hh*HD + lane] * 0.17677669529663687f;
    float m = -1e30f, l = 0.f, o = 0.f;
    int ntile = (rt0 + 71) >> 6;
    int krow = tid >> 3;
    int kc = (tid & 7) * 4;
    for (int jt = 0; jt < ntile; jt++) {
        int j0 = jt * 64;
        __syncthreads();
        #pragma unroll
        for (int half = 0; half < 2; half++) {
            int jl = krow + half*32;
            int jg = j0 + jl; if (jg > LL-1) jg = LL-1;
            const float* kp = base + (long)jg*3*DD + DD + hh*HD + kc;
            float4 k4 = *(const float4*)kp;
            float4 v4 = *(const float4*)(kp + DD);
            Ks[jl][kc]=k4.x; Ks[jl][kc+1]=k4.y; Ks[jl][kc+2]=k4.z; Ks[jl][kc+3]=k4.w;
            Vs[jl][kc]=v4.x; Vs[jl][kc+1]=v4.y; Vs[jl][kc+2]=v4.z; Vs[jl][kc+3]=v4.w;
        }
        __syncthreads();
        #pragma unroll
        for (int c = 0; c < 2; c++) {
            int jbase = j0 + c*32;
            if (jbase > r) break;
            int jl = c*32 + lane;
            int jg = jbase + lane;
            float sc = 0.f;
            #pragma unroll
            for (int d = 0; d < 32; d++) sc += qs[w][d] * Ks[jl][d];
            if (jg > r) sc = -1e30f;
            float cm = sc;
            #pragma unroll
            for (int s = 16; s; s >>= 1) cm = fmaxf(cm, __shfl_xor_sync(0xffffffffu, cm, s));
            float mn = fmaxf(m, cm);
            float p = (jg <= r) ? expf(sc - mn) : 0.f;
            __syncwarp();
            ps[w][lane] = p;
            float psum = p;
            #pragma unroll
            for (int s = 16; s; s >>= 1) psum += __shfl_xor_sync(0xffffffffu, psum, s);
            float corr = expf(m - mn);
            l = l*corr + psum; o *= corr; m = mn;
            __syncwarp();
            int jmax = min(32, r - jbase + 1);
            for (int jj = 0; jj < jmax; jj++)
                o += ps[w][jj] * Vs[c*32 + jj][lane];
        }
    }
    g_ao[((long)b*LL + r)*DD + hh*HD + lane] = o / l;
}

// ---------------- bias grads: gb2 = colsum(e), gb1 = colsum(dz) ------------
__global__ void k_gbias() {
    int b = blockIdx.x, tid = threadIdx.x;
    if (blockIdx.y == 0) {
        const float* p = g_e + (long)b*LL*DD + tid;
        float s = 0.f;
        for (int t = 0; t < LL; t++) s += p[(long)t*DD];
        g_gb2[b*DD + tid] = s;
    } else {
        const float* p = g_dz + (long)b*LL*HM + tid;
        float s = 0.f;
        for (int t = 0; t < LL; t++) s += p[(long)t*HM];
        g_gb1[b*HM + tid] = s;
    }
}

// ---------------- gate coefficients ----------------------------------------
__global__ void k_coef(const float* __restrict__ cW1, const float* __restrict__ cb1,
                       const float* __restrict__ cW2, const float* __restrict__ cb2) {
    int b = blockIdx.x, tid = threadIdx.x;
    __shared__ float ybar[DD];
    __shared__ float ch[CHN];
    float sum = 0.f;
    const float* yp = g_y + (long)b*LL*DD + tid;
    for (int t = 0; t < LL; t++) sum += yp[(long)t*DD];
    ybar[tid] = sum / (float)LL;
    __syncthreads();
    if (tid < CHN) {
        float a = cb1[tid];
        for (int d = 0; d < DD; d++) a += ybar[d] * cW1[d*CHN + tid];
        ch[tid] = a / (1.f + expf(-a));
    }
    __syncthreads();
    if (tid < 3) {
        float a = cb2[tid];
        for (int j = 0; j < CHN; j++) a += ch[j] * cW2[j*3 + tid];
        g_coef[b*3 + tid] = 1.f / (1.f + expf(-a));
    }
}

// ---------------- momentum + decay update ----------------------------------
__global__ void k_update() {
    long i = (long)blockIdx.x * blockDim.x + threadIdx.x;
    if (i >= (long)BB*PER) return;
    int b = (int)(i / PER), off = (int)(i % PER);
    float alpha = g_coef[b*3+0], eta = g_coef[b*3+1], theta = g_coef[b*3+2];
    float *fp, *mp, *gp;
    long idx;
    if (off < DD*HM)                   { fp = g_fastW1; mp = g_momW1; gp = g_gW1; idx = (long)b*DD*HM + off; }
    else if (off < DD*HM + HM)         { int o = off - DD*HM; fp = g_fastb1; mp = g_momb1; gp = g_gb1; idx = b*HM + o; }
    else if (off < DD*HM + HM + HM*DD) { int o = off - DD*HM - HM; fp = g_fastW2; mp = g_momW2; gp = g_gW2; idx = (long)b*HM*DD + o; }
    else                               { int o = off - DD*HM - HM - HM*DD; fp = g_fastb2; mp = g_momb2; gp = g_gb2; idx = b*DD + o; }
    float m = eta * mp[idx] - theta * gp[idx];
    mp[idx] = m;
    fp[idx] = (1.f - alpha) * fp[idx] + m;
}

// ---------------------------------------------------------------------------
extern "C" void kernel_launch(void* const* d_in, const int* in_sizes, int n_in,
                              void* d_out, int out_size) {
    const float* x     = (const float*)d_in[0];
    const float* pers  = (const float*)d_in[1];
    const float* W_Q   = (const float*)d_in[2];
    const float* in_w  = (const float*)d_in[3];
    const float* in_b  = (const float*)d_in[4];
    const float* out_w = (const float*)d_in[5];
    const float* out_b = (const float*)d_in[6];
    const float* mW1   = (const float*)d_in[7];
    const float* mb1   = (const float*)d_in[8];
    const float* mW2   = (const float*)d_in[9];
    const float* mb2   = (const float*)d_in[10];
    const float* W_K   = (const float*)d_in[11];
    const float* W_V   = (const float*)d_in[12];
    const float* cW1   = (const float*)d_in[13];
    const float* cb1   = (const float*)d_in[14];
    const float* cW2   = (const float*)d_in[15];
    const float* cb2   = (const float*)d_in[16];
    float* out = (float*)d_out;

    float *fW1, *fb1, *fW2, *fb2, *pQall, *pWkv, *pAttn, *pH1, *pQkv, *pAo, *pY;
    float *pKV, *pZ, *pS, *pDz, *pE, *pGW1, *pGW2;
    cudaGetSymbolAddress((void**)&fW1, g_fastW1);
    cudaGetSymbolAddress((void**)&fb1, g_fastb1);
    cudaGetSymbolAddress((void**)&fW2, g_fastW2);
    cudaGetSymbolAddress((void**)&fb2, g_fastb2);
    cudaGetSymbolAddress((void**)&pQall, g_qall);
    cudaGetSymbolAddress((void**)&pWkv, g_Wkv);
    cudaGetSymbolAddress((void**)&pAttn, g_attn);
    cudaGetSymbolAddress((void**)&pH1, g_h1);
    cudaGetSymbolAddress((void**)&pQkv, g_qkv);
    cudaGetSymbolAddress((void**)&pAo, g_ao);
    cudaGetSymbolAddress((void**)&pY, g_y);
    cudaGetSymbolAddress((void**)&pKV, g_kv);
    cudaGetSymbolAddress((void**)&pZ, g_z);
    cudaGetSymbolAddress((void**)&pS, g_s);
    cudaGetSymbolAddress((void**)&pDz, g_dz);
    cudaGetSymbolAddress((void**)&pE, g_e);
    cudaGetSymbolAddress((void**)&pGW1, g_gW1);
    cudaGetSymbolAddress((void**)&pGW2, g_gW2);

    k_init<<<((long)BB*DD*HM + 255)/256, 256>>>(mW1, mb1, mW2, mb2, pers, W_K, W_V);

    // Q_all = x @ W_Q  (M = 32768)
    t_gemm<false,false,false,0><<<dim3(DD/64, (BB*SS)/64, 1), 256>>>(
        x, W_Q, nullptr, pQall, nullptr, nullptr,
        BB*SS, DD, DD, DD, DD, DD, 0, 0L, 0L, 0L, 0, 0L);

    for (int s = 0; s < NSEG; s++) {
        int s0 = s * CC;
        k_packx<<<(BB*CC*DD + 255)/256, 256>>>(x, s0);

        // h1 = silu(q_seg @ fastW1 + fastb1)
        t_gemm<false,false,true,1><<<dim3(HM/64, CC/64, BB), 256>>>(
            pQall + (long)s0*DD, fW1, fb1, pH1, nullptr, nullptr,
            CC, HM, DD, DD, HM, HM, 0, (long)SS*DD, (long)DD*HM, (long)CC*HM, HM, 0L);
        // h = h1 @ fastW2 + fastb2 -> attn_in rows [PP, PP+CC)
        t_gemm<false,false,true,0><<<dim3(DD/64, CC/64, BB), 256>>>(
            pH1, fW2, fb2, pAttn + PP*DD, nullptr, nullptr,
            CC, DD, HM, HM, DD, DD, 0, (long)CC*HM, (long)HM*DD, (long)LL*DD, DD, 0L);

        // qkv = attn_in @ in_proj_w^T + in_proj_b  (M = 4224)
        t_gemm<false,true,true,0><<<dim3((3*DD)/64, (BB*LL)/64, 1), 256>>>(
            pAttn, in_w, in_b, pQkv, nullptr, nullptr,
            BB*LL, 3*DD, DD, DD, DD, 3*DD, 0, 0L, 0L, 0L, 0, 0L);
        k_attn2<<<BB*NH*(LL/8), 256>>>();
        // y = ao @ out_proj_w^T + out_proj_b
        t_gemm<false,true,true,0><<<dim3(DD/64, (BB*LL)/64, 1), 256>>>(
            pAo, out_w, out_b, pY, nullptr, nullptr,
            BB*LL, DD, DD, DD, DD, DD, 0, 0L, 0L, 0L, 0, 0L);
        // [k|v] = y @ Wkv
        t_gemm<false,false,false,0><<<dim3((2*DD)/64, (BB*LL)/64, 1), 256>>>(
            pY, pWkv, nullptr, pKV, nullptr, nullptr,
            BB*LL, 2*DD, DD, DD, 2*DD, 2*DD, 0, 0L, 0L, 0L, 0, 0L);

        // z = k @ W1 + b1 ; s = silu(z)
        t_gemm<false,false,true,2><<<dim3(HM/64, (LL+63)/64, BB), 256>>>(
            pKV, fW1, fb1, pZ, nullptr, pS,
            LL, HM, DD, 2*DD, HM, HM, 0, (long)LL*2*DD, (long)DD*HM, (long)LL*HM, HM, 0L);
        // e = (s @ W2 + b2 - v) * LD_INV
        t_gemm<false,false,true,3><<<dim3(DD/64, (LL+63)/64, BB), 256>>>(
            pS, fW2, fb2, pE, pKV + DD, nullptr,
            LL, DD, HM, HM, DD, DD, 2*DD, (long)LL*HM, (long)HM*DD, (long)LL*DD, DD, (long)LL*2*DD);
        // dz = (e @ W2^T) * silu'(z)
        t_gemm<false,true,false,4><<<dim3(HM/64, (LL+63)/64, BB), 256>>>(
            pE, fW2, nullptr, pDz, pZ, nullptr,
            LL, HM, DD, DD, DD, HM, HM, (long)LL*DD, (long)HM*DD, (long)LL*HM, 0, (long)LL*HM);
        // gW2[h,d] = sum_t s[t,h] e[t,d]
        t_gemm<true,false,false,0><<<dim3(DD/64, HM/64, BB), 256>>>(
            pS, pE, nullptr, pGW2, nullptr, nullptr,
            HM, DD, LL, HM, DD, DD, 0, (long)LL*HM, (long)LL*DD, (long)HM*DD, 0, 0L);
        // gW1[d,h] = sum_t k[t,d] dz[t,h]
        t_gemm<true,false,false,0><<<dim3(HM/64, DD/64, BB), 256>>>(
            pKV, pDz, nullptr, pGW1, nullptr, nullptr,
            DD, HM, LL, 2*DD, HM, HM, 0, (long)LL*2*DD, (long)LL*HM, (long)DD*HM, 0, 0L);
        k_gbias<<<dim3(BB, 2), 256>>>();

        k_coef<<<BB, 256>>>(cW1, cb1, cW2, cb2);
        k_update<<<((long)BB*PER + 255)/256, 256>>>();

        // final: mem_apply(updated weights, y_last) gated by y_last -> out
        t_gemm<false,false,true,1><<<dim3(HM/64, CC/64, BB), 256>>>(
            pY + (long)(PP+CC)*DD, fW1, fb1, pH1, nullptr, nullptr,
            CC, HM, DD, DD, HM, HM, 0, (long)LL*DD, (long)DD*HM, (long)CC*HM, HM, 0L);
        t_gemm<false,false,true,5><<<dim3(DD/64, CC/64, BB), 256>>>(
            pH1, fW2, fb2, out + (long)s0*DD, pY + (long)(PP+CC)*DD, nullptr,
            CC, DD, HM, HM, DD, DD, DD, (long)CC*HM, (long)HM*DD, (long)SS*DD, DD, (long)LL*DD);
    }
}

// round 11
// speedup vs baseline: 1.2779x; 1.0184x over previous
#include <cuda_runtime.h>
#include <cuda_bf16.h>
#include <math.h>

#define BB 16
#define SS 2048
#define DD 256
#define HM 256
#define PP 8
#define CHN 16
#define CC 128
#define LL 264            // PP + 2*CC
#define NH 8
#define HD 32
#define NSEG 16
#define PER (DD*HM + HM + HM*DD + DD)
#define LD_INV (1.0f/((float)LL*(float)DD))

#define APITCH 264        // 64-row A/H smem pitch (bf16 elems)
#define BPITCH 26         // B stage pitch (bf16 elems), 13 words -> conflict-free
#define SMEM_MLP (4*64*APITCH*2 + 2*2*256*BPITCH*2 + 2*256*4)

// ---------------- persistent scratch (device globals; no allocation) -------
__device__ __align__(16) float g_fastW1[BB*DD*HM];
__device__ __align__(16) float g_fastb1[BB*HM];
__device__ __align__(16) float g_fastW2[BB*HM*DD];
__device__ __align__(16) float g_fastb2[BB*DD];
__device__ __align__(16) float g_momW1[BB*DD*HM];
__device__ __align__(16) float g_momb1[BB*HM];
__device__ __align__(16) float g_momW2[BB*HM*DD];
__device__ __align__(16) float g_momb2[BB*DD];
__device__ __align__(16) float g_gW1[BB*DD*HM];
__device__ __align__(16) float g_gb1[BB*HM];
__device__ __align__(16) float g_gW2[BB*HM*DD];
__device__ __align__(16) float g_gb2[BB*DD];
__device__ __align__(16) float g_qall[BB*SS*DD];
__device__ __align__(16) float g_Wkv[DD*2*DD];
__device__ __align__(16) float g_attnA[NSEG*BB*LL*DD];   // per-seg attn_in
__device__ __align__(16) float g_qkv[BB*LL*3*DD];
__device__ __align__(16) float g_ao[BB*LL*DD];
__device__ __align__(16) float g_y[BB*LL*DD];
__device__ __align__(16) float g_kv[BB*LL*2*DD];
__device__ __align__(16) float g_s[BB*LL*HM];
__device__ __align__(16) float g_dz[BB*LL*HM];
__device__ __align__(16) float g_e[BB*LL*DD];
__device__ float g_coef[BB*3];

// ---------------- bf16 split helpers (truncation hi + rn lo) ---------------
__device__ __forceinline__ void split2(float x0, float x1, unsigned& ph, unsigned& pl) {
    unsigned b0 = __float_as_uint(x0), b1 = __float_as_uint(x1);
    ph = __byte_perm(b0, b1, 0x7632);
    float l0 = x0 - __uint_as_float(b0 & 0xFFFF0000u);
    float l1 = x1 - __uint_as_float(b1 & 0xFFFF0000u);
    __nv_bfloat162 t = __float22bfloat162_rn(make_float2(l0, l1));
    pl = *(unsigned*)&t;
}
__device__ __forceinline__ void split1(float x, __nv_bfloat16& h, __nv_bfloat16& l) {
    unsigned b = __float_as_uint(x);
    unsigned short hs = (unsigned short)(b >> 16);
    h = *reinterpret_cast<__nv_bfloat16*>(&hs);
    l = __float2bfloat16(x - __uint_as_float(b & 0xFFFF0000u));
}
#define MMA_BF16(d, a, bq) \
    asm volatile("mma.sync.aligned.m16n8k16.row.col.f32.bf16.bf16.f32 " \
        "{%0,%1,%2,%3}, {%4,%5,%6,%7}, {%8,%9}, {%0,%1,%2,%3};" \
        : "+f"(d[0]), "+f"(d[1]), "+f"(d[2]), "+f"(d[3]) \
        : "r"(a[0]), "r"(a[1]), "r"(a[2]), "r"(a[3]), "r"(bq[0]), "r"(bq[1]))

// ---------------- init: fast weights, momentum, Wkv concat -----------------
__global__ void k_init(const float* __restrict__ mW1, const float* __restrict__ mb1,
                       const float* __restrict__ mW2, const float* __restrict__ mb2,
                       const float* __restrict__ W_K, const float* __restrict__ W_V) {
    long i = (long)blockIdx.x * blockDim.x + threadIdx.x;
    if (i < (long)BB*DD*HM) {
        g_fastW1[i] = mW1[i % (DD*HM)]; g_momW1[i] = 0.f;
        g_fastW2[i] = mW2[i % (HM*DD)]; g_momW2[i] = 0.f;
    }
    if (i < BB*HM) { g_fastb1[i] = mb1[i % HM]; g_momb1[i] = 0.f; }
    if (i < BB*DD) { g_fastb2[i] = mb2[i % DD]; g_momb2[i] = 0.f; }
    if (i < DD*2*DD) {
        int k = (int)(i >> 9), n = (int)(i & 511);
        g_Wkv[i] = (n < DD) ? W_K[k*DD + n] : W_V[k*DD + n - DD];
    }
}

// ---------------- prepack pers + x slices for ALL segments -----------------
__global__ void k_prepack(const float* __restrict__ x, const float* __restrict__ pers) {
    long i = (long)blockIdx.x * blockDim.x + threadIdx.x;
    const long TOT = (long)NSEG*BB*(PP+CC)*DD;
    if (i >= TOT) return;
    int d = (int)(i % DD);
    long t1 = i / DD;
    int t = (int)(t1 % (PP+CC));
    long t2 = t1 / (PP+CC);
    int b = (int)(t2 % BB);
    int s = (int)(t2 / BB);
    int row = (t < PP) ? t : (t + CC);
    float v = (t < PP) ? pers[t*DD + d]
                       : x[(long)b*SS*DD + (long)(s*CC + t - PP)*DD + d];
    g_attnA[(((long)s*BB + b)*LL + row)*DD + d] = v;
}

// ---------------- fused memory-MLP kernel ----------------------------------
// Per block: 64 rows x full 256 cols, A resident in smem (split bf16).
// MODE 0: h = silu(A@W1+b1)@W2+b2 -> O1
// MODE 1: z=A@W1+b1; s=silu(z)->O1; e=(s@W2+b2-v)*LD_INV->O2; dz=(e@W2^T)*silu'(z)->O3
// MODE 2: O1 = (silu(A@W1+b1)@W2+b2) * A     (gate by y)
template<int MODE>
__global__ __launch_bounds__(256) void k_mlp(
    const float* __restrict__ Ain, float* __restrict__ O1,
    float* __restrict__ O2, float* __restrict__ O3,
    const float* __restrict__ Vin,
    int M, int lda, long sA, long sO1)
{
    extern __shared__ __align__(16) char smraw[];
    __nv_bfloat16* Ah  = (__nv_bfloat16*)smraw;
    __nv_bfloat16* Al  = Ah + 64*APITCH;
    __nv_bfloat16* Hh  = Al + 64*APITCH;
    __nv_bfloat16* Hl  = Hh + 64*APITCH;
    __nv_bfloat16* BsH = Hl + 64*APITCH;            // [2][256][BPITCH]
    __nv_bfloat16* BsL = BsH + 2*256*BPITCH;
    float* biasS = (float*)(BsL + 2*256*BPITCH);    // [2][256]

    int b = blockIdx.z;
    int m0 = blockIdx.y * 64;
    int tid = threadIdx.x;
    const float* W1 = g_fastW1 + (long)b*DD*HM;
    const float* W2 = g_fastW2 + (long)b*HM*DD;
    Ain += (long)b * sA;
    O1  += (long)b * sO1;
    if (MODE == 1) {
        O2  += (long)b * (long)LL*DD;
        O3  += (long)b * (long)LL*HM;
        Vin += (long)b * (long)LL*2*DD;
    }

    biasS[tid]       = g_fastb1[b*HM + tid];
    biasS[256 + tid] = g_fastb2[b*DD + tid];

    // stage A (64 x 256) split into Ah/Al
    #pragma unroll
    for (int j = 0; j < 16; j++) {
        int f = tid + j*256;
        int r = f >> 6, c4 = (f & 63) * 4;
        int rr = m0 + r; if (rr >= M) rr = M - 1;
        float4 v = *(const float4*)(Ain + (long)rr*lda + c4);
        unsigned ph0, pl0, ph1, pl1;
        split2(v.x, v.y, ph0, pl0); split2(v.z, v.w, ph1, pl1);
        *(unsigned*)&Ah[r*APITCH + c4]     = ph0;
        *(unsigned*)&Ah[r*APITCH + c4 + 2] = ph1;
        *(unsigned*)&Al[r*APITCH + c4]     = pl0;
        *(unsigned*)&Al[r*APITCH + c4 + 2] = pl1;
    }
    __syncthreads();

    int warp = tid >> 5, lane = tid & 31;
    int wm = warp & 1, wn = warp >> 1;       // warp tile 32m x 64n
    int g = lane >> 2, tq = lane & 3;
    float acc[2][8][4];
    float vv[16];

    auto loadB = [&](const float* W, int ldw, int tb, int kt) {
        if (tb) {
            const float* p = W + (long)tid*ldw + kt*16;
            #pragma unroll
            for (int j = 0; j < 4; j++) {
                float4 t4 = *(const float4*)(p + j*4);
                vv[j*4]=t4.x; vv[j*4+1]=t4.y; vv[j*4+2]=t4.z; vv[j*4+3]=t4.w;
            }
        } else {
            const float* p = W + (long)(kt*16)*ldw + tid;
            #pragma unroll
            for (int k = 0; k < 16; k++) vv[k] = p[(long)k*ldw];
        }
    };
    auto storeB = [&](int buf) {
        __nv_bfloat16* dh = BsH + (buf*256 + tid)*BPITCH;
        __nv_bfloat16* dl = BsL + (buf*256 + tid)*BPITCH;
        #pragma unroll
        for (int k = 0; k < 16; k += 2) {
            unsigned ph, pl;
            split2(vv[k], vv[k+1], ph, pl);
            *(unsigned*)&dh[k] = ph;
            *(unsigned*)&dl[k] = pl;
        }
    };
    auto run_gemm = [&](const __nv_bfloat16* Xh, const __nv_bfloat16* Xl,
                        const float* W, int ldw, int tb) {
        #pragma unroll
        for (int mi = 0; mi < 2; mi++)
            #pragma unroll
            for (int ni = 0; ni < 8; ni++)
                #pragma unroll
                for (int e = 0; e < 4; e++) acc[mi][ni][e] = 0.f;
        loadB(W, ldw, tb, 0);
        storeB(0);
        __syncthreads();
        for (int kt = 0; kt < 16; kt++) {
            int cur = kt & 1;
            if (kt < 15) loadB(W, ldw, tb, kt + 1);
            int ko = kt*16 + tq*2;
            unsigned ah[2][4], al[2][4];
            #pragma unroll
            for (int mi = 0; mi < 2; mi++) {
                int r = wm*32 + mi*16 + g;
                ah[mi][0] = *(const unsigned*)&Xh[r*APITCH + ko];
                ah[mi][1] = *(const unsigned*)&Xh[(r+8)*APITCH + ko];
                ah[mi][2] = *(const unsigned*)&Xh[r*APITCH + ko + 8];
                ah[mi][3] = *(const unsigned*)&Xh[(r+8)*APITCH + ko + 8];
                al[mi][0] = *(const unsigned*)&Xl[r*APITCH + ko];
                al[mi][1] = *(const unsigned*)&Xl[(r+8)*APITCH + ko];
                al[mi][2] = *(const unsigned*)&Xl[r*APITCH + ko + 8];
                al[mi][3] = *(const unsigned*)&Xl[(r+8)*APITCH + ko + 8];
            }
            #pragma unroll
            for (int ni = 0; ni < 8; ni++) {
                int nr = wn*64 + ni*8 + g;
                const __nv_bfloat16* ph = BsH + (cur*256 + nr)*BPITCH + tq*2;
                const __nv_bfloat16* pl = BsL + (cur*256 + nr)*BPITCH + tq*2;
                unsigned bh[2], bl[2];
                bh[0] = *(const unsigned*)ph; bh[1] = *(const unsigned*)(ph + 8);
                bl[0] = *(const unsigned*)pl; bl[1] = *(const unsigned*)(pl + 8);
                #pragma unroll
                for (int mi = 0; mi < 2; mi++) {
                    MMA_BF16(acc[mi][ni], ah[mi], bh);
                    MMA_BF16(acc[mi][ni], al[mi], bh);
                    MMA_BF16(acc[mi][ni], ah[mi], bl);
                }
            }
            if (kt < 15) storeB(cur ^ 1);
            __syncthreads();
        }
    };

    // ---- GEMM1: z = A @ W1 + b1 ; h1/s = silu(z) -> H buffers ----
    run_gemm(Ah, Al, W1, HM, 0);
    #pragma unroll
    for (int mi = 0; mi < 2; mi++)
    #pragma unroll
    for (int ni = 0; ni < 8; ni++)
    #pragma unroll
    for (int h2 = 0; h2 < 2; h2++) {
        int rl = wm*32 + mi*16 + g + h2*8;
        int c  = wn*64 + ni*8 + tq*2;
        float z0 = acc[mi][ni][h2*2+0] + biasS[c];
        float z1 = acc[mi][ni][h2*2+1] + biasS[c+1];
        float s0v = z0 / (1.f + expf(-z0));
        float s1v = z1 / (1.f + expf(-z1));
        unsigned ph, pl;
        split2(s0v, s1v, ph, pl);
        *(unsigned*)&Hh[rl*APITCH + c] = ph;
        *(unsigned*)&Hl[rl*APITCH + c] = pl;
        if (MODE == 1) {
            split2(z0, z1, ph, pl);              // keep z (A is dead)
            *(unsigned*)&Ah[rl*APITCH + c] = ph;
            *(unsigned*)&Al[rl*APITCH + c] = pl;
            if (m0 + rl < M)
                *(float2*)&O1[(long)(m0+rl)*256 + c] = make_float2(s0v, s1v);
        }
    }
    __syncthreads();

    // ---- GEMM2: pred = s @ W2 + b2 ----
    run_gemm(Hh, Hl, W2, DD, 0);
    #pragma unroll
    for (int mi = 0; mi < 2; mi++)
    #pragma unroll
    for (int ni = 0; ni < 8; ni++)
    #pragma unroll
    for (int h2 = 0; h2 < 2; h2++) {
        int rl = wm*32 + mi*16 + g + h2*8;
        int c  = wn*64 + ni*8 + tq*2;
        float v0 = acc[mi][ni][h2*2+0] + biasS[256 + c];
        float v1 = acc[mi][ni][h2*2+1] + biasS[256 + c + 1];
        bool valid = (m0 + rl) < M;
        long ro = (long)(m0 + rl) * 256 + c;
        if (MODE == 0) {
            if (valid) *(float2*)&O1[ro] = make_float2(v0, v1);
        } else if (MODE == 2) {
            float y0 = __bfloat162float(Ah[rl*APITCH + c])   + __bfloat162float(Al[rl*APITCH + c]);
            float y1 = __bfloat162float(Ah[rl*APITCH + c+1]) + __bfloat162float(Al[rl*APITCH + c+1]);
            if (valid) *(float2*)&O1[ro] = make_float2(v0*y0, v1*y1);
        } else {
            float e0 = 0.f, e1 = 0.f;
            if (valid) {
                float2 vr = *(const float2*)&Vin[(long)(m0+rl)*(2*DD) + c];
                e0 = (v0 - vr.x) * LD_INV;
                e1 = (v1 - vr.y) * LD_INV;
                *(float2*)&O2[ro] = make_float2(e0, e1);
            }
            unsigned ph, pl;
            split2(e0, e1, ph, pl);              // e -> H buffers (s is dead)
            *(unsigned*)&Hh[rl*APITCH + c] = ph;
            *(unsigned*)&Hl[rl*APITCH + c] = pl;
        }
    }

    // ---- GEMM3 (MODE 1): dz = (e @ W2^T) * silu'(z) ----
    if (MODE == 1) {
        __syncthreads();
        run_gemm(Hh, Hl, W2, DD, 1);
        #pragma unroll
        for (int mi = 0; mi < 2; mi++)
        #pragma unroll
        for (int ni = 0; ni < 8; ni++)
        #pragma unroll
        for (int h2 = 0; h2 < 2; h2++) {
            int rl = wm*32 + mi*16 + g + h2*8;
            int c  = wn*64 + ni*8 + tq*2;
            if (m0 + rl < M) {
                float z0 = __bfloat162float(Ah[rl*APITCH + c])   + __bfloat162float(Al[rl*APITCH + c]);
                float z1 = __bfloat162float(Ah[rl*APITCH + c+1]) + __bfloat162float(Al[rl*APITCH + c+1]);
                float sg0 = 1.f/(1.f+expf(-z0)), sg1 = 1.f/(1.f+expf(-z1));
                float d0 = acc[mi][ni][h2*2+0] * sg0 * (1.f + z0*(1.f - sg0));
                float d1 = acc[mi][ni][h2*2+1] * sg1 * (1.f + z1*(1.f - sg1));
                *(float2*)&O3[(long)(m0+rl)*256 + c] = make_float2(d0, d1);
            }
        }
    }
}

#define KP 24

// ---------------- tensor-core GEMM (bf16x3), 64x64 tile, 256 thr -----------
// TA: A is [K][M]; else [M][K].  TB: B is [N][K]; else [K][N].
// GB (TA only): gb[n] += colsum over K of B (bias gradients), blockIdx.y==0.
template<bool TA, bool TB, bool BIAS, bool GB>
__global__ __launch_bounds__(256) void t_gemm(
        const float* __restrict__ A, const float* __restrict__ Bw,
        const float* __restrict__ bias, float* __restrict__ C,
        float* __restrict__ gb,
        int M, int N, int K, int lda, int ldb, int ldc,
        long sA, long sB, long sC, int sBias, int sGB) {
    __shared__ __align__(16) __nv_bfloat16 AsH[2][64][KP];
    __shared__ __align__(16) __nv_bfloat16 AsL[2][64][KP];
    __shared__ __align__(16) __nv_bfloat16 BsH[2][64][KP];
    __shared__ __align__(16) __nv_bfloat16 BsL[2][64][KP];
    int b = blockIdx.z;
    A  += (long)b * sA;
    Bw += (long)b * sB;
    C  += (long)b * sC;
    if (BIAS) bias += (long)b * sBias;
    int tid = threadIdx.x;
    int n0 = blockIdx.x * 64, m0 = blockIdx.y * 64;
    int nkt = (K + 15) >> 4;

    float ar[4], br[4];
    int am  = tid >> 2, akq = (tid & 3) * 4;
    int akr = tid >> 4, amq = (tid & 15) * 4;
    int bkr = tid >> 4, bnq = (tid & 15) * 4;
    int bn  = tid >> 2, bkq = (tid & 3) * 4;

    const float* Aptr;
    if (!TA) { int r = m0 + am; if (r >= M) r = M - 1; Aptr = A + (long)r*lda; }

    auto readA = [&](int kt) {
        if (!TA) {
            float4 v = *(const float4*)(Aptr + kt*16 + akq);
            ar[0]=v.x; ar[1]=v.y; ar[2]=v.z; ar[3]=v.w;
        } else {
            int kr = kt*16 + akr;
            if (kr < K) {
                float4 v = *(const float4*)(A + (long)kr*lda + m0 + amq);
                ar[0]=v.x; ar[1]=v.y; ar[2]=v.z; ar[3]=v.w;
            } else { ar[0]=ar[1]=ar[2]=ar[3]=0.f; }
        }
    };
    auto readB = [&](int kt) {
        if (!TB) {
            int kr = kt*16 + bkr;
            if (kr < K) {
                float4 v = *(const float4*)(Bw + (long)kr*ldb + n0 + bnq);
                br[0]=v.x; br[1]=v.y; br[2]=v.z; br[3]=v.w;
            } else { br[0]=br[1]=br[2]=br[3]=0.f; }
        } else {
            float4 v = *(const float4*)(Bw + (long)(n0+bn)*ldb + kt*16 + bkq);
            br[0]=v.x; br[1]=v.y; br[2]=v.z; br[3]=v.w;
        }
    };
    auto storeA = [&](int buf) {
        if (!TA) {
            unsigned ph0, pl0, ph1, pl1;
            split2(ar[0], ar[1], ph0, pl0);
            split2(ar[2], ar[3], ph1, pl1);
            *(unsigned*)&AsH[buf][am][akq]   = ph0;
            *(unsigned*)&AsH[buf][am][akq+2] = ph1;
            *(unsigned*)&AsL[buf][am][akq]   = pl0;
            *(unsigned*)&AsL[buf][am][akq+2] = pl1;
        } else {
            #pragma unroll
            for (int j = 0; j < 4; j++) {
                __nv_bfloat16 h, l;
                split1(ar[j], h, l);
                AsH[buf][amq+j][akr] = h;
                AsL[buf][amq+j][akr] = l;
            }
        }
    };
    auto storeB = [&](int buf) {
        if (!TB) {
            #pragma unroll
            for (int j = 0; j < 4; j++) {
                __nv_bfloat16 h, l;
                split1(br[j], h, l);
                BsH[buf][bnq+j][bkr] = h;
                BsL[buf][bnq+j][bkr] = l;
            }
        } else {
            unsigned ph0, pl0, ph1, pl1;
            split2(br[0], br[1], ph0, pl0);
            split2(br[2], br[3], ph1, pl1);
            *(unsigned*)&BsH[buf][bn][bkq]   = ph0;
            *(unsigned*)&BsH[buf][bn][bkq+2] = ph1;
            *(unsigned*)&BsL[buf][bn][bkq]   = pl0;
            *(unsigned*)&BsL[buf][bn][bkq+2] = pl1;
        }
    };

    int warp = tid >> 5, lane = tid & 31;
    int wm = warp & 1, wn = warp >> 1;
    int g = lane >> 2, tq = lane & 3;
    int ko = tq * 2;
    float acc[2][2][4] = {};
    float csum = 0.f;

    readA(0); readB(0);
    storeA(0); storeB(0);
    __syncthreads();

    for (int kt = 0; kt < nkt; kt++) {
        int cur = kt & 1;
        if (kt + 1 < nkt) { readA(kt+1); readB(kt+1); }
        unsigned ah[2][4], al[2][4], bh[2][2], bl[2][2];
        #pragma unroll
        for (int mi = 0; mi < 2; mi++) {
            int r = wm*32 + mi*16 + g;
            ah[mi][0] = *(const unsigned*)&AsH[cur][r][ko];
            ah[mi][1] = *(const unsigned*)&AsH[cur][r+8][ko];
            ah[mi][2] = *(const unsigned*)&AsH[cur][r][ko+8];
            ah[mi][3] = *(const unsigned*)&AsH[cur][r+8][ko+8];
            al[mi][0] = *(const unsigned*)&AsL[cur][r][ko];
            al[mi][1] = *(const unsigned*)&AsL[cur][r+8][ko];
            al[mi][2] = *(const unsigned*)&AsL[cur][r][ko+8];
            al[mi][3] = *(const unsigned*)&AsL[cur][r+8][ko+8];
        }
        #pragma unroll
        for (int ni = 0; ni < 2; ni++) {
            int nr = wn*16 + ni*8 + g;
            bh[ni][0] = *(const unsigned*)&BsH[cur][nr][ko];
            bh[ni][1] = *(const unsigned*)&BsH[cur][nr][ko+8];
            bl[ni][0] = *(const unsigned*)&BsL[cur][nr][ko];
            bl[ni][1] = *(const unsigned*)&BsL[cur][nr][ko+8];
        }
        if (GB && tid < 64) {
            #pragma unroll
            for (int k2 = 0; k2 < 16; k2 += 2) {
                float2 hf = __bfloat1622float2(*(const __nv_bfloat162*)&BsH[cur][tid][k2]);
                float2 lf = __bfloat1622float2(*(const __nv_bfloat162*)&BsL[cur][tid][k2]);
                csum += hf.x + hf.y + lf.x + lf.y;
            }
        }
        #pragma unroll
        for (int mi = 0; mi < 2; mi++)
            #pragma unroll
            for (int ni = 0; ni < 2; ni++) {
                MMA_BF16(acc[mi][ni], ah[mi], bh[ni]);
                MMA_BF16(acc[mi][ni], al[mi], bh[ni]);
                MMA_BF16(acc[mi][ni], ah[mi], bl[ni]);
            }
        if (kt + 1 < nkt) { storeA(cur ^ 1); storeB(cur ^ 1); }
        __syncthreads();
    }

    if (GB && blockIdx.y == 0 && tid < 64)
        gb[(long)b*sGB + n0 + tid] = csum;

    #pragma unroll
    for (int mi = 0; mi < 2; mi++) {
        #pragma unroll
        for (int ni = 0; ni < 2; ni++) {
            int c0 = n0 + wn*16 + ni*8 + tq*2;
            float bv0 = 0.f, bv1 = 0.f;
            if (BIAS) { bv0 = bias[c0]; bv1 = bias[c0+1]; }
            #pragma unroll
            for (int h2 = 0; h2 < 2; h2++) {
                int r = m0 + wm*32 + mi*16 + g + h2*8;
                if (r < M) {
                    C[(long)r*ldc + c0]   = acc[mi][ni][h2*2+0] + bv0;
                    C[(long)r*ldc + c0+1] = acc[mi][ni][h2*2+1] + bv1;
                }
            }
        }
    }
}

// ---------------- attention: block = (b, head, 8-row tile), smem K/V -------
__global__ void k_attn2() {
    __shared__ float Ks[64][33];
    __shared__ float Vs[64][33];
    __shared__ float qs[8][32];
    __shared__ float ps[8][32];
    int blk = blockIdx.x;
    int tile = blk % (LL/8);
    int hh = (blk / (LL/8)) % NH;
    int b  = blk / ((LL/8)*NH);
    int rt0 = tile * 8;
    int tid = threadIdx.x;
    int w = tid >> 5, lane = tid & 31;
    int r = rt0 + w;
    const float* base = g_qkv + (long)b*LL*3*DD;
    qs[w][lane] = base[(long)r*3*DD + hh*HD + lane] * 0.17677669529663687f;
    float m = -1e30f, l = 0.f, o = 0.f;
    int ntile = (rt0 + 71) >> 6;
    int krow = tid >> 3;
    int kc = (tid & 7) * 4;
    for (int jt = 0; jt < ntile; jt++) {
        int j0 = jt * 64;
        __syncthreads();
        #pragma unroll
        for (int half = 0; half < 2; half++) {
            int jl = krow + half*32;
            int jg = j0 + jl; if (jg > LL-1) jg = LL-1;
            const float* kp = base + (long)jg*3*DD + DD + hh*HD + kc;
            float4 k4 = *(const float4*)kp;
            float4 v4 = *(const float4*)(kp + DD);
            Ks[jl][kc]=k4.x; Ks[jl][kc+1]=k4.y; Ks[jl][kc+2]=k4.z; Ks[jl][kc+3]=k4.w;
            Vs[jl][kc]=v4.x; Vs[jl][kc+1]=v4.y; Vs[jl][kc+2]=v4.z; Vs[jl][kc+3]=v4.w;
        }
        __syncthreads();
        #pragma unroll
        for (int c = 0; c < 2; c++) {
            int jbase = j0 + c*32;
            if (jbase > r) break;
            int jl = c*32 + lane;
            int jg = jbase + lane;
            float sc = 0.f;
            #pragma unroll
            for (int d = 0; d < 32; d++) sc += qs[w][d] * Ks[jl][d];
            if (jg > r) sc = -1e30f;
            float cm = sc;
            #pragma unroll
            for (int s = 16; s; s >>= 1) cm = fmaxf(cm, __shfl_xor_sync(0xffffffffu, cm, s));
            float mn = fmaxf(m, cm);
            float p = (jg <= r) ? expf(sc - mn) : 0.f;
            __syncwarp();
            ps[w][lane] = p;
            float psum = p;
            #pragma unroll
            for (int s = 16; s; s >>= 1) psum += __shfl_xor_sync(0xffffffffu, psum, s);
            float corr = expf(m - mn);
            l = l*corr + psum; o *= corr; m = mn;
            __syncwarp();
            int jmax = min(32, r - jbase + 1);
            for (int jj = 0; jj < jmax; jj++)
                o += ps[w][jj] * Vs[c*32 + jj][lane];
        }
    }
    g_ao[((long)b*LL + r)*DD + hh*HD + lane] = o / l;
}

// ---------------- gate coefficients ----------------------------------------
__global__ void k_coef(const float* __restrict__ cW1, const float* __restrict__ cb1,
                       const float* __restrict__ cW2, const float* __restrict__ cb2) {
    int b = blockIdx.x, tid = threadIdx.x;
    __shared__ float ybar[DD];
    __shared__ float ch[CHN];
    float sum = 0.f;
    const float* yp = g_y + (long)b*LL*DD + tid;
    for (int t = 0; t < LL; t++) sum += yp[(long)t*DD];
    ybar[tid] = sum / (float)LL;
    __syncthreads();
    if (tid < CHN) {
        float a = cb1[tid];
        for (int d = 0; d < DD; d++) a += ybar[d] * cW1[d*CHN + tid];
        ch[tid] = a / (1.f + expf(-a));
    }
    __syncthreads();
    if (tid < 3) {
        float a = cb2[tid];
        for (int j = 0; j < CHN; j++) a += ch[j] * cW2[j*3 + tid];
        g_coef[b*3 + tid] = 1.f / (1.f + expf(-a));
    }
}

// ---------------- momentum + decay update ----------------------------------
__global__ void k_update() {
    long i = (long)blockIdx.x * blockDim.x + threadIdx.x;
    if (i >= (long)BB*PER) return;
    int b = (int)(i / PER), off = (int)(i % PER);
    float alpha = g_coef[b*3+0], eta = g_coef[b*3+1], theta = g_coef[b*3+2];
    float *fp, *mp, *gp;
    long idx;
    if (off < DD*HM)                   { fp = g_fastW1; mp = g_momW1; gp = g_gW1; idx = (long)b*DD*HM + off; }
    else if (off < DD*HM + HM)         { int o = off - DD*HM; fp = g_fastb1; mp = g_momb1; gp = g_gb1; idx = b*HM + o; }
    else if (off < DD*HM + HM + HM*DD) { int o = off - DD*HM - HM; fp = g_fastW2; mp = g_momW2; gp = g_gW2; idx = (long)b*HM*DD + o; }
    else                               { int o = off - DD*HM - HM - HM*DD; fp = g_fastb2; mp = g_momb2; gp = g_gb2; idx = b*DD + o; }
    float m = eta * mp[idx] - theta * gp[idx];
    mp[idx] = m;
    fp[idx] = (1.f - alpha) * fp[idx] + m;
}

// ---------------------------------------------------------------------------
extern "C" void kernel_launch(void* const* d_in, const int* in_sizes, int n_in,
                              void* d_out, int out_size) {
    const float* x     = (const float*)d_in[0];
    const float* pers  = (const float*)d_in[1];
    const float* W_Q   = (const float*)d_in[2];
    const float* in_w  = (const float*)d_in[3];
    const float* in_b  = (const float*)d_in[4];
    const float* out_w = (const float*)d_in[5];
    const float* out_b = (const float*)d_in[6];
    const float* mW1   = (const float*)d_in[7];
    const float* mb1   = (const float*)d_in[8];
    const float* mW2   = (const float*)d_in[9];
    const float* mb2   = (const float*)d_in[10];
    const float* W_K   = (const float*)d_in[11];
    const float* W_V   = (const float*)d_in[12];
    const float* cW1   = (const float*)d_in[13];
    const float* cb1   = (const float*)d_in[14];
    const float* cW2   = (const float*)d_in[15];
    const float* cb2   = (const float*)d_in[16];
    float* out = (float*)d_out;

    cudaFuncSetAttribute(k_mlp<0>, cudaFuncAttributeMaxDynamicSharedMemorySize, SMEM_MLP);
    cudaFuncSetAttribute(k_mlp<1>, cudaFuncAttributeMaxDynamicSharedMemorySize, SMEM_MLP);
    cudaFuncSetAttribute(k_mlp<2>, cudaFuncAttributeMaxDynamicSharedMemorySize, SMEM_MLP);

    float *pQall, *pWkv, *pAttnA, *pQkv, *pAo, *pY, *pKV, *pS, *pDz, *pE;
    float *pGW1, *pGW2, *pGb1, *pGb2;
    cudaGetSymbolAddress((void**)&pQall, g_qall);
    cudaGetSymbolAddress((void**)&pWkv, g_Wkv);
    cudaGetSymbolAddress((void**)&pAttnA, g_attnA);
    cudaGetSymbolAddress((void**)&pQkv, g_qkv);
    cudaGetSymbolAddress((void**)&pAo, g_ao);
    cudaGetSymbolAddress((void**)&pY, g_y);
    cudaGetSymbolAddress((void**)&pKV, g_kv);
    cudaGetSymbolAddress((void**)&pS, g_s);
    cudaGetSymbolAddress((void**)&pDz, g_dz);
    cudaGetSymbolAddress((void**)&pE, g_e);
    cudaGetSymbolAddress((void**)&pGW1, g_gW1);
    cudaGetSymbolAddress((void**)&pGW2, g_gW2);
    cudaGetSymbolAddress((void**)&pGb1, g_gb1);
    cudaGetSymbolAddress((void**)&pGb2, g_gb2);

    k_init<<<((long)BB*DD*HM + 255)/256, 256>>>(mW1, mb1, mW2, mb2, W_K, W_V);
    k_prepack<<<((long)NSEG*BB*(PP+CC)*DD + 255)/256, 256>>>(x, pers);

    // Q_all = x @ W_Q  (M = 32768)
    t_gemm<false,false,false,false><<<dim3(DD/64, (BB*SS)/64, 1), 256>>>(
        x, W_Q, nullptr, pQall, nullptr,
        BB*SS, DD, DD, DD, DD, DD, 0L, 0L, 0L, 0, 0);

    for (int s = 0; s < NSEG; s++) {
        int s0 = s * CC;
        float* pAttnS = pAttnA + (long)s*BB*LL*DD;

        // h = silu(q_seg @ W1 + b1) @ W2 + b2  -> attn rows [PP, PP+CC)
        k_mlp<0><<<dim3(1, CC/64, BB), 256, SMEM_MLP>>>(
            pQall + (long)s0*DD, pAttnS + PP*DD, nullptr, nullptr, nullptr,
            CC, DD, (long)SS*DD, (long)LL*DD);

        // qkv = attn_in @ in_proj_w^T + in_proj_b  (M = 4224)
        t_gemm<false,true,true,false><<<dim3((3*DD)/64, (BB*LL)/64, 1), 256>>>(
            pAttnS, in_w, in_b, pQkv, nullptr,
            BB*LL, 3*DD, DD, DD, DD, 3*DD, 0L, 0L, 0L, 0, 0);
        k_attn2<<<BB*NH*(LL/8), 256>>>();
        // y = ao @ out_proj_w^T + out_proj_b
        t_gemm<false,true,true,false><<<dim3(DD/64, (BB*LL)/64, 1), 256>>>(
            pAo, out_w, out_b, pY, nullptr,
            BB*LL, DD, DD, DD, DD, DD, 0L, 0L, 0L, 0, 0);
        k_coef<<<BB, 256>>>(cW1, cb1, cW2, cb2);
        // [k|v] = y @ Wkv
        t_gemm<false,false,false,false><<<dim3((2*DD)/64, (BB*LL)/64, 1), 256>>>(
            pY, pWkv, nullptr, pKV, nullptr,
            BB*LL, 2*DD, DD, DD, 2*DD, 2*DD, 0L, 0L, 0L, 0, 0);

        // fused grad: z, s, e, dz in one kernel
        k_mlp<1><<<dim3(1, (LL+63)/64, BB), 256, SMEM_MLP>>>(
            pKV, pS, pE, pDz, pKV + DD,
            LL, 2*DD, (long)LL*2*DD, (long)LL*HM);

        // gW2[h,d] = sum_t s[t,h] e[t,d]  (+ gb2 = colsum e)
        t_gemm<true,false,false,true><<<dim3(DD/64, HM/64, BB), 256>>>(
            pS, pE, nullptr, pGW2, pGb2,
            HM, DD, LL, HM, DD, DD, (long)LL*HM, (long)LL*DD, (long)HM*DD, 0, DD);
        // gW1[d,h] = sum_t k[t,d] dz[t,h]  (+ gb1 = colsum dz)
        t_gemm<true,false,false,true><<<dim3(HM/64, DD/64, BB), 256>>>(
            pKV, pDz, nullptr, pGW1, pGb1,
            DD, HM, LL, 2*DD, HM, HM, (long)LL*2*DD, (long)LL*HM, (long)DD*HM, 0, HM);

        k_update<<<((long)BB*PER + 255)/256, 256>>>();

        // final: out = y_last * (silu(y_last @ W1 + b1) @ W2 + b2)   [updated weights]
        k_mlp<2><<<dim3(1, CC/64, BB), 256, SMEM_MLP>>>(
            pY + (long)(PP+CC)*DD, out + (long)s0*DD, nullptr, nullptr, nullptr,
            CC, DD, (long)LL*DD, (long)SS*DD);
    }
}

// round 12
// speedup vs baseline: 1.2940x; 1.0125x over previous
#include <cuda_runtime.h>
#include <cuda_bf16.h>
#include <math.h>

#define BB 16
#define SS 2048
#define DD 256
#define HM 256
#define PP 8
#define CHN 16
#define CC 128
#define LL 264            // PP + 2*CC
#define NH 8
#define HD 32
#define NSEG 16
#define PER (DD*HM + HM + HM*DD + DD)
#define LD_INV (1.0f/((float)LL*(float)DD))

#define APITCH 264        // 64-row A/H smem pitch (bf16 elems)
#define BPITCH 26         // B stage pitch (bf16 elems)
#define SMEM_MLP (4*64*APITCH*2 + 2*2*256*BPITCH*2 + 2*256*4)

// ---------------- persistent scratch (device globals; no allocation) -------
__device__ __align__(16) float g_fastW1[BB*DD*HM];
__device__ __align__(16) float g_fastb1[BB*HM];
__device__ __align__(16) float g_fastW2[BB*HM*DD];
__device__ __align__(16) float g_fastb2[BB*DD];
__device__ __align__(16) float g_momW1[BB*DD*HM];
__device__ __align__(16) float g_momb1[BB*HM];
__device__ __align__(16) float g_momW2[BB*HM*DD];
__device__ __align__(16) float g_momb2[BB*DD];
__device__ __align__(16) float g_gW1[BB*DD*HM];
__device__ __align__(16) float g_gb1[BB*HM];
__device__ __align__(16) float g_gW2[BB*HM*DD];
__device__ __align__(16) float g_gb2[BB*DD];
__device__ __align__(16) float g_qall[BB*SS*DD];
__device__ __align__(16) float g_Wkv[DD*2*DD];
__device__ __align__(16) float g_attnA[NSEG*BB*LL*DD];
__device__ __align__(16) float g_qkv[BB*LL*3*DD];
__device__ __align__(16) float g_ao[BB*LL*DD];
__device__ __align__(16) float g_y[BB*LL*DD];
__device__ __align__(16) float g_kv[BB*LL*2*DD];
__device__ __align__(16) float g_s[BB*LL*HM];
__device__ __align__(16) float g_dz[BB*LL*HM];
__device__ __align__(16) float g_e[BB*LL*DD];
__device__ float g_coef[BB*3];

// ---------------- bf16 split helpers (truncation hi + rn lo) ---------------
__device__ __forceinline__ void split2(float x0, float x1, unsigned& ph, unsigned& pl) {
    unsigned b0 = __float_as_uint(x0), b1 = __float_as_uint(x1);
    ph = __byte_perm(b0, b1, 0x7632);
    float l0 = x0 - __uint_as_float(b0 & 0xFFFF0000u);
    float l1 = x1 - __uint_as_float(b1 & 0xFFFF0000u);
    __nv_bfloat162 t = __float22bfloat162_rn(make_float2(l0, l1));
    pl = *(unsigned*)&t;
}
__device__ __forceinline__ void split1(float x, __nv_bfloat16& h, __nv_bfloat16& l) {
    unsigned b = __float_as_uint(x);
    unsigned short hs = (unsigned short)(b >> 16);
    h = *reinterpret_cast<__nv_bfloat16*>(&hs);
    l = __float2bfloat16(x - __uint_as_float(b & 0xFFFF0000u));
}
#define MMA_BF16(d, a, bq) \
    asm volatile("mma.sync.aligned.m16n8k16.row.col.f32.bf16.bf16.f32 " \
        "{%0,%1,%2,%3}, {%4,%5,%6,%7}, {%8,%9}, {%0,%1,%2,%3};" \
        : "+f"(d[0]), "+f"(d[1]), "+f"(d[2]), "+f"(d[3]) \
        : "r"(a[0]), "r"(a[1]), "r"(a[2]), "r"(a[3]), "r"(bq[0]), "r"(bq[1]))

// ---------------- init: fast weights, momentum, Wkv concat -----------------
__global__ void k_init(const float* __restrict__ mW1, const float* __restrict__ mb1,
                       const float* __restrict__ mW2, const float* __restrict__ mb2,
                       const float* __restrict__ W_K, const float* __restrict__ W_V) {
    long i = (long)blockIdx.x * blockDim.x + threadIdx.x;
    if (i < (long)BB*DD*HM) {
        g_fastW1[i] = mW1[i % (DD*HM)]; g_momW1[i] = 0.f;
        g_fastW2[i] = mW2[i % (HM*DD)]; g_momW2[i] = 0.f;
    }
    if (i < BB*HM) { g_fastb1[i] = mb1[i % HM]; g_momb1[i] = 0.f; }
    if (i < BB*DD) { g_fastb2[i] = mb2[i % DD]; g_momb2[i] = 0.f; }
    if (i < DD*2*DD) {
        int k = (int)(i >> 9), n = (int)(i & 511);
        g_Wkv[i] = (n < DD) ? W_K[k*DD + n] : W_V[k*DD + n - DD];
    }
}

// ---------------- prepack pers + x slices for ALL segments -----------------
__global__ void k_prepack(const float* __restrict__ x, const float* __restrict__ pers) {
    long i = (long)blockIdx.x * blockDim.x + threadIdx.x;
    const long TOT = (long)NSEG*BB*(PP+CC)*DD;
    if (i >= TOT) return;
    int d = (int)(i % DD);
    long t1 = i / DD;
    int t = (int)(t1 % (PP+CC));
    long t2 = t1 / (PP+CC);
    int b = (int)(t2 % BB);
    int s = (int)(t2 / BB);
    int row = (t < PP) ? t : (t + CC);
    float v = (t < PP) ? pers[t*DD + d]
                       : x[(long)b*SS*DD + (long)(s*CC + t - PP)*DD + d];
    g_attnA[(((long)s*BB + b)*LL + row)*DD + d] = v;
}

// ---------------- fused memory-MLP body (runtime mode) ---------------------
// mode 0: O1 = silu(A@W1+b1)@W2+b2
// mode 1: z=A@W1+b1; s=silu(z)->O1; e=(s@W2+b2-v)*LD_INV->O2; dz=(e@W2^T)*silu'(z)->O3
// mode 2: O1 = (silu(A@W1+b1)@W2+b2) * A
__device__ __forceinline__ void mlp_body(
    int mode, const float* Ain, float* O1, float* O2, float* O3,
    const float* Vin, int b, int m0, int M, int lda, long sA, long sO1)
{
    extern __shared__ __align__(16) char smraw[];
    __nv_bfloat16* Ah  = (__nv_bfloat16*)smraw;
    __nv_bfloat16* Al  = Ah + 64*APITCH;
    __nv_bfloat16* Hh  = Al + 64*APITCH;
    __nv_bfloat16* Hl  = Hh + 64*APITCH;
    __nv_bfloat16* BsH = Hl + 64*APITCH;            // [2][256][BPITCH]
    __nv_bfloat16* BsL = BsH + 2*256*BPITCH;
    float* biasS = (float*)(BsL + 2*256*BPITCH);    // [2][256]

    int tid = threadIdx.x;
    const float* W1 = g_fastW1 + (long)b*DD*HM;
    const float* W2 = g_fastW2 + (long)b*HM*DD;
    Ain += (long)b * sA;
    O1  += (long)b * sO1;
    if (mode == 1) {
        O2  += (long)b * (long)LL*DD;
        O3  += (long)b * (long)LL*HM;
        Vin += (long)b * (long)LL*2*DD;
    }

    biasS[tid]       = g_fastb1[b*HM + tid];
    biasS[256 + tid] = g_fastb2[b*DD + tid];

    // stage A (64 x 256) split into Ah/Al
    #pragma unroll
    for (int j = 0; j < 16; j++) {
        int f = tid + j*256;
        int r = f >> 6, c4 = (f & 63) * 4;
        int rr = m0 + r; if (rr >= M) rr = M - 1;
        float4 v = *(const float4*)(Ain + (long)rr*lda + c4);
        unsigned ph0, pl0, ph1, pl1;
        split2(v.x, v.y, ph0, pl0); split2(v.z, v.w, ph1, pl1);
        *(unsigned*)&Ah[r*APITCH + c4]     = ph0;
        *(unsigned*)&Ah[r*APITCH + c4 + 2] = ph1;
        *(unsigned*)&Al[r*APITCH + c4]     = pl0;
        *(unsigned*)&Al[r*APITCH + c4 + 2] = pl1;
    }
    __syncthreads();

    int warp = tid >> 5, lane = tid & 31;
    int wm = warp & 1, wn = warp >> 1;       // warp tile 32m x 64n
    int g = lane >> 2, tq = lane & 3;
    float acc[2][8][4];
    float vv0[16], vv1[16];

    auto loadB = [&](const float* W, int ldw, int tb, int kt, float* vv) {
        if (tb) {
            const float* p = W + (long)tid*ldw + kt*16;
            #pragma unroll
            for (int j = 0; j < 4; j++) {
                float4 t4 = *(const float4*)(p + j*4);
                vv[j*4]=t4.x; vv[j*4+1]=t4.y; vv[j*4+2]=t4.z; vv[j*4+3]=t4.w;
            }
        } else {
            const float* p = W + (long)(kt*16)*ldw + tid;
            #pragma unroll
            for (int k = 0; k < 16; k++) vv[k] = p[(long)k*ldw];
        }
    };
    auto storeB = [&](int buf, const float* vv) {
        __nv_bfloat16* dh = BsH + (buf*256 + tid)*BPITCH;
        __nv_bfloat16* dl = BsL + (buf*256 + tid)*BPITCH;
        #pragma unroll
        for (int k = 0; k < 16; k += 2) {
            unsigned ph, pl;
            split2(vv[k], vv[k+1], ph, pl);
            *(unsigned*)&dh[k] = ph;
            *(unsigned*)&dl[k] = pl;
        }
    };
    auto mma_tile = [&](const __nv_bfloat16* Xh, const __nv_bfloat16* Xl, int kt) {
        int cur = kt & 1;
        int ko = kt*16 + tq*2;
        unsigned ah[2][4], al[2][4];
        #pragma unroll
        for (int mi = 0; mi < 2; mi++) {
            int r = wm*32 + mi*16 + g;
            ah[mi][0] = *(const unsigned*)&Xh[r*APITCH + ko];
            ah[mi][1] = *(const unsigned*)&Xh[(r+8)*APITCH + ko];
            ah[mi][2] = *(const unsigned*)&Xh[r*APITCH + ko + 8];
            ah[mi][3] = *(const unsigned*)&Xh[(r+8)*APITCH + ko + 8];
            al[mi][0] = *(const unsigned*)&Xl[r*APITCH + ko];
            al[mi][1] = *(const unsigned*)&Xl[(r+8)*APITCH + ko];
            al[mi][2] = *(const unsigned*)&Xl[r*APITCH + ko + 8];
            al[mi][3] = *(const unsigned*)&Xl[(r+8)*APITCH + ko + 8];
        }
        #pragma unroll
        for (int ni = 0; ni < 8; ni++) {
            int nr = wn*64 + ni*8 + g;
            const __nv_bfloat16* ph = BsH + (cur*256 + nr)*BPITCH + tq*2;
            const __nv_bfloat16* pl = BsL + (cur*256 + nr)*BPITCH + tq*2;
            unsigned bh[2], bl[2];
            bh[0] = *(const unsigned*)ph; bh[1] = *(const unsigned*)(ph + 8);
            bl[0] = *(const unsigned*)pl; bl[1] = *(const unsigned*)(pl + 8);
            #pragma unroll
            for (int mi = 0; mi < 2; mi++) {
                MMA_BF16(acc[mi][ni], ah[mi], bh);
                MMA_BF16(acc[mi][ni], al[mi], bh);
                MMA_BF16(acc[mi][ni], ah[mi], bl);
            }
        }
    };
    auto run_gemm = [&](const __nv_bfloat16* Xh, const __nv_bfloat16* Xl,
                        const float* W, int ldw, int tb) {
        #pragma unroll
        for (int mi = 0; mi < 2; mi++)
            #pragma unroll
            for (int ni = 0; ni < 8; ni++)
                #pragma unroll
                for (int e = 0; e < 4; e++) acc[mi][ni][e] = 0.f;
        loadB(W, ldw, tb, 0, vv0);
        storeB(0, vv0);
        loadB(W, ldw, tb, 1, vv1);
        __syncthreads();
        int kt = 0;
        while (true) {
            if (kt + 2 < 16) loadB(W, ldw, tb, kt + 2, vv0);
            mma_tile(Xh, Xl, kt);
            if (kt + 1 < 16) storeB((kt + 1) & 1, vv1);
            __syncthreads();
            if (++kt >= 16) break;
            if (kt + 2 < 16) loadB(W, ldw, tb, kt + 2, vv1);
            mma_tile(Xh, Xl, kt);
            if (kt + 1 < 16) storeB((kt + 1) & 1, vv0);
            __syncthreads();
            if (++kt >= 16) break;
        }
    };

    // ---- GEMM1: z = A @ W1 + b1 ; h1/s = silu(z) -> H buffers ----
    run_gemm(Ah, Al, W1, HM, 0);
    #pragma unroll
    for (int mi = 0; mi < 2; mi++)
    #pragma unroll
    for (int ni = 0; ni < 8; ni++)
    #pragma unroll
    for (int h2 = 0; h2 < 2; h2++) {
        int rl = wm*32 + mi*16 + g + h2*8;
        int c  = wn*64 + ni*8 + tq*2;
        float z0 = acc[mi][ni][h2*2+0] + biasS[c];
        float z1 = acc[mi][ni][h2*2+1] + biasS[c+1];
        float s0v = z0 / (1.f + expf(-z0));
        float s1v = z1 / (1.f + expf(-z1));
        unsigned ph, pl;
        split2(s0v, s1v, ph, pl);
        *(unsigned*)&Hh[rl*APITCH + c] = ph;
        *(unsigned*)&Hl[rl*APITCH + c] = pl;
        if (mode == 1) {
            split2(z0, z1, ph, pl);              // keep z (A is dead)
            *(unsigned*)&Ah[rl*APITCH + c] = ph;
            *(unsigned*)&Al[rl*APITCH + c] = pl;
            if (m0 + rl < M)
                *(float2*)&O1[(long)(m0+rl)*256 + c] = make_float2(s0v, s1v);
        }
    }
    __syncthreads();

    // ---- GEMM2: pred = s @ W2 + b2 ----
    run_gemm(Hh, Hl, W2, DD, 0);
    #pragma unroll
    for (int mi = 0; mi < 2; mi++)
    #pragma unroll
    for (int ni = 0; ni < 8; ni++)
    #pragma unroll
    for (int h2 = 0; h2 < 2; h2++) {
        int rl = wm*32 + mi*16 + g + h2*8;
        int c  = wn*64 + ni*8 + tq*2;
        float v0 = acc[mi][ni][h2*2+0] + biasS[256 + c];
        float v1 = acc[mi][ni][h2*2+1] + biasS[256 + c + 1];
        bool valid = (m0 + rl) < M;
        long ro = (long)(m0 + rl) * 256 + c;
        if (mode == 0) {
            if (valid) *(float2*)&O1[ro] = make_float2(v0, v1);
        } else if (mode == 2) {
            float y0 = __bfloat162float(Ah[rl*APITCH + c])   + __bfloat162float(Al[rl*APITCH + c]);
            float y1 = __bfloat162float(Ah[rl*APITCH + c+1]) + __bfloat162float(Al[rl*APITCH + c+1]);
            if (valid) *(float2*)&O1[ro] = make_float2(v0*y0, v1*y1);
        } else {
            float e0 = 0.f, e1 = 0.f;
            if (valid) {
                float2 vr = *(const float2*)&Vin[(long)(m0+rl)*(2*DD) + c];
                e0 = (v0 - vr.x) * LD_INV;
                e1 = (v1 - vr.y) * LD_INV;
                *(float2*)&O2[ro] = make_float2(e0, e1);
            }
            unsigned ph, pl;
            split2(e0, e1, ph, pl);              // e -> H buffers (s is dead)
            *(unsigned*)&Hh[rl*APITCH + c] = ph;
            *(unsigned*)&Hl[rl*APITCH + c] = pl;
        }
    }

    // ---- GEMM3 (mode 1): dz = (e @ W2^T) * silu'(z) ----
    if (mode == 1) {
        __syncthreads();
        run_gemm(Hh, Hl, W2, DD, 1);
        #pragma unroll
        for (int mi = 0; mi < 2; mi++)
        #pragma unroll
        for (int ni = 0; ni < 8; ni++)
        #pragma unroll
        for (int h2 = 0; h2 < 2; h2++) {
            int rl = wm*32 + mi*16 + g + h2*8;
            int c  = wn*64 + ni*8 + tq*2;
            if (m0 + rl < M) {
                float z0 = __bfloat162float(Ah[rl*APITCH + c])   + __bfloat162float(Al[rl*APITCH + c]);
                float z1 = __bfloat162float(Ah[rl*APITCH + c+1]) + __bfloat162float(Al[rl*APITCH + c+1]);
                float sg0 = 1.f/(1.f+expf(-z0)), sg1 = 1.f/(1.f+expf(-z1));
                float d0 = acc[mi][ni][h2*2+0] * sg0 * (1.f + z0*(1.f - sg0));
                float d1 = acc[mi][ni][h2*2+1] * sg1 * (1.f + z1*(1.f - sg1));
                *(float2*)&O3[(long)(m0+rl)*256 + c] = make_float2(d0, d1);
            }
        }
    }
}

__global__ __launch_bounds__(256) void k_mlp_single(
    int mode, const float* Ain, float* O1, float* O2, float* O3,
    const float* Vin, int M, int lda, long sA, long sO1)
{
    mlp_body(mode, Ain, O1, O2, O3, Vin, blockIdx.z, blockIdx.y*64, M, lda, sA, sO1);
}

// dual launch: z<BB -> mode2 (gated out, seg s); z>=BB -> mode0 (h, seg s+1)
__global__ __launch_bounds__(256) void k_mlp_dual(
    const float* A2, float* O2out, const float* A0, float* O0out,
    long sA2, long sO2, long sA0, long sO0)
{
    int z = blockIdx.z;
    if (z < BB) mlp_body(2, A2, O2out, nullptr, nullptr, nullptr, z,      blockIdx.y*64, CC, DD, sA2, sO2);
    else        mlp_body(0, A0, O0out, nullptr, nullptr, nullptr, z - BB, blockIdx.y*64, CC, DD, sA0, sO0);
}

#define KP 24

// ---------------- tensor-core GEMM (bf16x3), 64x64 tile, pipelined ---------
// A is [M][K].  TB: B is [N][K]; else [K][N].  K % 16 == 0, K >= 32.
template<bool TB, bool BIAS>
__global__ __launch_bounds__(256) void t_gemm(
        const float* __restrict__ A, const float* __restrict__ Bw,
        const float* __restrict__ bias, float* __restrict__ C,
        int M, int N, int K, int lda, int ldb, int ldc,
        long sA, long sB, long sC, int sBias) {
    __shared__ __align__(16) __nv_bfloat16 AsH[2][64][KP];
    __shared__ __align__(16) __nv_bfloat16 AsL[2][64][KP];
    __shared__ __align__(16) __nv_bfloat16 BsH[2][64][KP];
    __shared__ __align__(16) __nv_bfloat16 BsL[2][64][KP];
    int b = blockIdx.z;
    A  += (long)b * sA;
    Bw += (long)b * sB;
    C  += (long)b * sC;
    if (BIAS) bias += (long)b * sBias;
    int tid = threadIdx.x;
    int n0 = blockIdx.x * 64, m0 = blockIdx.y * 64;
    int nkt = K >> 4;

    int am  = tid >> 2, akq = (tid & 3) * 4;
    int bkr = tid >> 4, bnq = (tid & 15) * 4;
    int bn  = tid >> 2, bkq = (tid & 3) * 4;

    int r0 = m0 + am; if (r0 >= M) r0 = M - 1;
    const float* Aptr = A + (long)r0*lda;

    auto readAr = [&](int kt, float* ar) {
        float4 v = *(const float4*)(Aptr + kt*16 + akq);
        ar[0]=v.x; ar[1]=v.y; ar[2]=v.z; ar[3]=v.w;
    };
    auto readBr = [&](int kt, float* br) {
        if (!TB) {
            float4 v = *(const float4*)(Bw + (long)(kt*16 + bkr)*ldb + n0 + bnq);
            br[0]=v.x; br[1]=v.y; br[2]=v.z; br[3]=v.w;
        } else {
            float4 v = *(const float4*)(Bw + (long)(n0+bn)*ldb + kt*16 + bkq);
            br[0]=v.x; br[1]=v.y; br[2]=v.z; br[3]=v.w;
        }
    };
    auto storeAr = [&](int buf, const float* ar) {
        unsigned ph0, pl0, ph1, pl1;
        split2(ar[0], ar[1], ph0, pl0);
        split2(ar[2], ar[3], ph1, pl1);
        *(unsigned*)&AsH[buf][am][akq]   = ph0;
        *(unsigned*)&AsH[buf][am][akq+2] = ph1;
        *(unsigned*)&AsL[buf][am][akq]   = pl0;
        *(unsigned*)&AsL[buf][am][akq+2] = pl1;
    };
    auto storeBr = [&](int buf, const float* br) {
        if (!TB) {
            #pragma unroll
            for (int j = 0; j < 4; j++) {
                __nv_bfloat16 h, l;
                split1(br[j], h, l);
                BsH[buf][bnq+j][bkr] = h;
                BsL[buf][bnq+j][bkr] = l;
            }
        } else {
            unsigned ph0, pl0, ph1, pl1;
            split2(br[0], br[1], ph0, pl0);
            split2(br[2], br[3], ph1, pl1);
            *(unsigned*)&BsH[buf][bn][bkq]   = ph0;
            *(unsigned*)&BsH[buf][bn][bkq+2] = ph1;
            *(unsigned*)&BsL[buf][bn][bkq]   = pl0;
            *(unsigned*)&BsL[buf][bn][bkq+2] = pl1;
        }
    };

    int warp = tid >> 5, lane = tid & 31;
    int wm = warp & 1, wn = warp >> 1;
    int g = lane >> 2, tq = lane & 3;
    int ko = tq * 2;
    float acc[2][2][4] = {};

    auto mma_on = [&](int cur) {
        unsigned ah[2][4], al[2][4], bh[2][2], bl[2][2];
        #pragma unroll
        for (int mi = 0; mi < 2; mi++) {
            int r = wm*32 + mi*16 + g;
            ah[mi][0] = *(const unsigned*)&AsH[cur][r][ko];
            ah[mi][1] = *(const unsigned*)&AsH[cur][r+8][ko];
            ah[mi][2] = *(const unsigned*)&AsH[cur][r][ko+8];
            ah[mi][3] = *(const unsigned*)&AsH[cur][r+8][ko+8];
            al[mi][0] = *(const unsigned*)&AsL[cur][r][ko];
            al[mi][1] = *(const unsigned*)&AsL[cur][r+8][ko];
            al[mi][2] = *(const unsigned*)&AsL[cur][r][ko+8];
            al[mi][3] = *(const unsigned*)&AsL[cur][r+8][ko+8];
        }
        #pragma unroll
        for (int ni = 0; ni < 2; ni++) {
            int nr = wn*16 + ni*8 + g;
            bh[ni][0] = *(const unsigned*)&BsH[cur][nr][ko];
            bh[ni][1] = *(const unsigned*)&BsH[cur][nr][ko+8];
            bl[ni][0] = *(const unsigned*)&BsL[cur][nr][ko];
            bl[ni][1] = *(const unsigned*)&BsL[cur][nr][ko+8];
        }
        #pragma unroll
        for (int mi = 0; mi < 2; mi++)
            #pragma unroll
            for (int ni = 0; ni < 2; ni++) {
                MMA_BF16(acc[mi][ni], ah[mi], bh[ni]);
                MMA_BF16(acc[mi][ni], al[mi], bh[ni]);
                MMA_BF16(acc[mi][ni], ah[mi], bl[ni]);
            }
    };

    float a0[4], b0r[4], a1[4], b1r[4];
    readAr(0, a0); readBr(0, b0r);
    storeAr(0, a0); storeBr(0, b0r);
    readAr(1, a1); readBr(1, b1r);
    __syncthreads();
    int kt = 0;
    while (true) {
        if (kt + 2 < nkt) { readAr(kt+2, a0); readBr(kt+2, b0r); }
        mma_on(kt & 1);
        if (kt + 1 < nkt) { storeAr((kt+1) & 1, a1); storeBr((kt+1) & 1, b1r); }
        __syncthreads();
        if (++kt >= nkt) break;
        if (kt + 2 < nkt) { readAr(kt+2, a1); readBr(kt+2, b1r); }
        mma_on(kt & 1);
        if (kt + 1 < nkt) { storeAr((kt+1) & 1, a0); storeBr((kt+1) & 1, b0r); }
        __syncthreads();
        if (++kt >= nkt) break;
    }

    #pragma unroll
    for (int mi = 0; mi < 2; mi++) {
        #pragma unroll
        for (int ni = 0; ni < 2; ni++) {
            int c0 = n0 + wn*16 + ni*8 + tq*2;
            float bv0 = 0.f, bv1 = 0.f;
            if (BIAS) { bv0 = bias[c0]; bv1 = bias[c0+1]; }
            #pragma unroll
            for (int h2 = 0; h2 < 2; h2++) {
                int r = m0 + wm*32 + mi*16 + g + h2*8;
                if (r < M) {
                    C[(long)r*ldc + c0]   = acc[mi][ni][h2*2+0] + bv0;
                    C[(long)r*ldc + c0+1] = acc[mi][ni][h2*2+1] + bv1;
                }
            }
        }
    }
}

// ---------------- fused grad GEMM pair: gW2+gb2 (z<16) / gW1+gb1 (z>=16) ---
// C[m][n] = sum_t A[t][m]*B[t][n], K = LL = 264 (nkt = 17, tail guarded).
__global__ __launch_bounds__(256) void k_grad() {
    __shared__ __align__(16) __nv_bfloat16 AsH[2][64][KP];
    __shared__ __align__(16) __nv_bfloat16 AsL[2][64][KP];
    __shared__ __align__(16) __nv_bfloat16 BsH[2][64][KP];
    __shared__ __align__(16) __nv_bfloat16 BsL[2][64][KP];
    int z = blockIdx.z;
    int b = z & (BB-1);
    bool sel = z >= BB;
    const float *A, *B;
    float *C, *gb;
    int lda, ldb;
    if (!sel) { A = g_s  + (long)b*LL*HM;   B = g_e  + (long)b*LL*DD; C = g_gW2 + (long)b*HM*DD; gb = g_gb2 + b*DD; lda = HM;   ldb = DD; }
    else      { A = g_kv + (long)b*LL*2*DD; B = g_dz + (long)b*LL*HM; C = g_gW1 + (long)b*DD*HM; gb = g_gb1 + b*HM; lda = 2*DD; ldb = HM; }
    const int K = LL, nkt = 17;
    int tid = threadIdx.x;
    int n0 = blockIdx.x * 64, m0 = blockIdx.y * 64;

    int akr = tid >> 4, amq = (tid & 15) * 4;
    int bkr = tid >> 4, bnq = (tid & 15) * 4;

    auto readAr = [&](int kt, float* ar) {
        int kr = kt*16 + akr;
        if (kr < K) {
            float4 v = *(const float4*)(A + (long)kr*lda + m0 + amq);
            ar[0]=v.x; ar[1]=v.y; ar[2]=v.z; ar[3]=v.w;
        } else { ar[0]=ar[1]=ar[2]=ar[3]=0.f; }
    };
    auto readBr = [&](int kt, float* br) {
        int kr = kt*16 + bkr;
        if (kr < K) {
            float4 v = *(const float4*)(B + (long)kr*ldb + n0 + bnq);
            br[0]=v.x; br[1]=v.y; br[2]=v.z; br[3]=v.w;
        } else { br[0]=br[1]=br[2]=br[3]=0.f; }
    };
    auto storeAr = [&](int buf, const float* ar) {
        #pragma unroll
        for (int j = 0; j < 4; j++) {
            __nv_bfloat16 h, l;
            split1(ar[j], h, l);
            AsH[buf][amq+j][akr] = h;
            AsL[buf][amq+j][akr] = l;
        }
    };
    auto storeBr = [&](int buf, const float* br) {
        #pragma unroll
        for (int j = 0; j < 4; j++) {
            __nv_bfloat16 h, l;
            split1(br[j], h, l);
            BsH[buf][bnq+j][bkr] = h;
            BsL[buf][bnq+j][bkr] = l;
        }
    };

    int warp = tid >> 5, lane = tid & 31;
    int wm = warp & 1, wn = warp >> 1;
    int g = lane >> 2, tq = lane & 3;
    int ko = tq * 2;
    float acc[2][2][4] = {};
    float csum = 0.f;

    auto mma_on = [&](int cur) {
        unsigned ah[2][4], al[2][4], bh[2][2], bl[2][2];
        #pragma unroll
        for (int mi = 0; mi < 2; mi++) {
            int r = wm*32 + mi*16 + g;
            ah[mi][0] = *(const unsigned*)&AsH[cur][r][ko];
            ah[mi][1] = *(const unsigned*)&AsH[cur][r+8][ko];
            ah[mi][2] = *(const unsigned*)&AsH[cur][r][ko+8];
            ah[mi][3] = *(const unsigned*)&AsH[cur][r+8][ko+8];
            al[mi][0] = *(const unsigned*)&AsL[cur][r][ko];
            al[mi][1] = *(const unsigned*)&AsL[cur][r+8][ko];
            al[mi][2] = *(const unsigned*)&AsL[cur][r][ko+8];
            al[mi][3] = *(const unsigned*)&AsL[cur][r+8][ko+8];
        }
        #pragma unroll
        for (int ni = 0; ni < 2; ni++) {
            int nr = wn*16 + ni*8 + g;
            bh[ni][0] = *(const unsigned*)&BsH[cur][nr][ko];
            bh[ni][1] = *(const unsigned*)&BsH[cur][nr][ko+8];
            bl[ni][0] = *(const unsigned*)&BsL[cur][nr][ko];
            bl[ni][1] = *(const unsigned*)&BsL[cur][nr][ko+8];
        }
        if (tid < 64) {
            #pragma unroll
            for (int k2 = 0; k2 < 16; k2 += 2) {
                float2 hf = __bfloat1622float2(*(const __nv_bfloat162*)&BsH[cur][tid][k2]);
                float2 lf = __bfloat1622float2(*(const __nv_bfloat162*)&BsL[cur][tid][k2]);
                csum += hf.x + hf.y + lf.x + lf.y;
            }
        }
        #pragma unroll
        for (int mi = 0; mi < 2; mi++)
            #pragma unroll
            for (int ni = 0; ni < 2; ni++) {
                MMA_BF16(acc[mi][ni], ah[mi], bh[ni]);
                MMA_BF16(acc[mi][ni], al[mi], bh[ni]);
                MMA_BF16(acc[mi][ni], ah[mi], bl[ni]);
            }
    };

    float a0[4], b0r[4], a1[4], b1r[4];
    readAr(0, a0); readBr(0, b0r);
    storeAr(0, a0); storeBr(0, b0r);
    readAr(1, a1); readBr(1, b1r);
    __syncthreads();
    int kt = 0;
    while (true) {
        if (kt + 2 < nkt) { readAr(kt+2, a0); readBr(kt+2, b0r); }
        mma_on(kt & 1);
        if (kt + 1 < nkt) { storeAr((kt+1) & 1, a1); storeBr((kt+1) & 1, b1r); }
        __syncthreads();
        if (++kt >= nkt) break;
        if (kt + 2 < nkt) { readAr(kt+2, a1); readBr(kt+2, b1r); }
        mma_on(kt & 1);
        if (kt + 1 < nkt) { storeAr((kt+1) & 1, a0); storeBr((kt+1) & 1, b0r); }
        __syncthreads();
        if (++kt >= nkt) break;
    }

    if (blockIdx.y == 0 && tid < 64)
        gb[n0 + tid] = csum;

    #pragma unroll
    for (int mi = 0; mi < 2; mi++)
        #pragma unroll
        for (int ni = 0; ni < 2; ni++) {
            int c0 = n0 + wn*16 + ni*8 + tq*2;
            #pragma unroll
            for (int h2 = 0; h2 < 2; h2++) {
                int r = m0 + wm*32 + mi*16 + g + h2*8;
                C[(long)r*256 + c0]   = acc[mi][ni][h2*2+0];
                C[(long)r*256 + c0+1] = acc[mi][ni][h2*2+1];
            }
        }
}

// ---------------- attention: block = (b, head, 8-row tile), smem K/V -------
__global__ void k_attn2() {
    __shared__ float Ks[64][33];
    __shared__ float Vs[64][33];
    __shared__ float qs[8][32];
    __shared__ float ps[8][32];
    int blk = blockIdx.x;
    int tile = blk % (LL/8);
    int hh = (blk / (LL/8)) % NH;
    int b  = blk / ((LL/8)*NH);
    int rt0 = tile * 8;
    int tid = threadIdx.x;
    int w = tid >> 5, lane = tid & 31;
    int r = rt0 + w;
    const float* base = g_qkv + (long)b*LL*3*DD;
    qs[w][lane] = base[(long)r*3*DD + hh*HD + lane] * 0.17677669529663687f;
    float m = -1e30f, l = 0.f, o = 0.f;
    int ntile = (rt0 + 71) >> 6;
    int krow = tid >> 3;
    int kc = (tid & 7) * 4;
    for (int jt = 0; jt < ntile; jt++) {
        int j0 = jt * 64;
        __syncthreads();
        #pragma unroll
        for (int half = 0; half < 2; half++) {
            int jl = krow + half*32;
            int jg = j0 + jl; if (jg > LL-1) jg = LL-1;
            const float* kp = base + (long)jg*3*DD + DD + hh*HD + kc;
            float4 k4 = *(const float4*)kp;
            float4 v4 = *(const float4*)(kp + DD);
            Ks[jl][kc]=k4.x; Ks[jl][kc+1]=k4.y; Ks[jl][kc+2]=k4.z; Ks[jl][kc+3]=k4.w;
            Vs[jl][kc]=v4.x; Vs[jl][kc+1]=v4.y; Vs[jl][kc+2]=v4.z; Vs[jl][kc+3]=v4.w;
        }
        __syncthreads();
        #pragma unroll
        for (int c = 0; c < 2; c++) {
            int jbase = j0 + c*32;
            if (jbase > r) break;
            int jl = c*32 + lane;
            int jg = jbase + lane;
            float sc = 0.f;
            #pragma unroll
            for (int d = 0; d < 32; d++) sc += qs[w][d] * Ks[jl][d];
            if (jg > r) sc = -1e30f;
            float cm = sc;
            #pragma unroll
            for (int s = 16; s; s >>= 1) cm = fmaxf(cm, __shfl_xor_sync(0xffffffffu, cm, s));
            float mn = fmaxf(m, cm);
            float p = (jg <= r) ? expf(sc - mn) : 0.f;
            __syncwarp();
            ps[w][lane] = p;
            float psum = p;
            #pragma unroll
            for (int s = 16; s; s >>= 1) psum += __shfl_xor_sync(0xffffffffu, psum, s);
            float corr = expf(m - mn);
            l = l*corr + psum; o *= corr; m = mn;
            __syncwarp();
            int jmax = min(32, r - jbase + 1);
            for (int jj = 0; jj < jmax; jj++)
                o += ps[w][jj] * Vs[c*32 + jj][lane];
        }
    }
    g_ao[((long)b*LL + r)*DD + hh*HD + lane] = o / l;
}

// ---------------- gate coefficients ----------------------------------------
__global__ void k_coef(const float* __restrict__ cW1, const float* __restrict__ cb1,
                       const float* __restrict__ cW2, const float* __restrict__ cb2) {
    int b = blockIdx.x, tid = threadIdx.x;
    __shared__ float ybar[DD];
    __shared__ float ch[CHN];
    float sum = 0.f;
    const float* yp = g_y + (long)b*LL*DD + tid;
    for (int t = 0; t < LL; t++) sum += yp[(long)t*DD];
    ybar[tid] = sum / (float)LL;
    __syncthreads();
    if (tid < CHN) {
        float a = cb1[tid];
        for (int d = 0; d < DD; d++) a += ybar[d] * cW1[d*CHN + tid];
        ch[tid] = a / (1.f + expf(-a));
    }
    __syncthreads();
    if (tid < 3) {
        float a = cb2[tid];
        for (int j = 0; j < CHN; j++) a += ch[j] * cW2[j*3 + tid];
        g_coef[b*3 + tid] = 1.f / (1.f + expf(-a));
    }
}

// ---------------- momentum + decay update ----------------------------------
__global__ void k_update() {
    long i = (long)blockIdx.x * blockDim.x + threadIdx.x;
    if (i >= (long)BB*PER) return;
    int b = (int)(i / PER), off = (int)(i % PER);
    float alpha = g_coef[b*3+0], eta = g_coef[b*3+1], theta = g_coef[b*3+2];
    float *fp, *mp, *gp;
    long idx;
    if (off < DD*HM)                   { fp = g_fastW1; mp = g_momW1; gp = g_gW1; idx = (long)b*DD*HM + off; }
    else if (off < DD*HM + HM)         { int o = off - DD*HM; fp = g_fastb1; mp = g_momb1; gp = g_gb1; idx = b*HM + o; }
    else if (off < DD*HM + HM + HM*DD) { int o = off - DD*HM - HM; fp = g_fastW2; mp = g_momW2; gp = g_gW2; idx = (long)b*HM*DD + o; }
    else                               { int o = off - DD*HM - HM - HM*DD; fp = g_fastb2; mp = g_momb2; gp = g_gb2; idx = b*DD + o; }
    float m = eta * mp[idx] - theta * gp[idx];
    mp[idx] = m;
    fp[idx] = (1.f - alpha) * fp[idx] + m;
}

// ---------------------------------------------------------------------------
extern "C" void kernel_launch(void* const* d_in, const int* in_sizes, int n_in,
                              void* d_out, int out_size) {
    const float* x     = (const float*)d_in[0];
    const float* pers  = (const float*)d_in[1];
    const float* W_Q   = (const float*)d_in[2];
    const float* in_w  = (const float*)d_in[3];
    const float* in_b  = (const float*)d_in[4];
    const float* out_w = (const float*)d_in[5];
    const float* out_b = (const float*)d_in[6];
    const float* mW1   = (const float*)d_in[7];
    const float* mb1   = (const float*)d_in[8];
    const float* mW2   = (const float*)d_in[9];
    const float* mb2   = (const float*)d_in[10];
    const float* W_K   = (const float*)d_in[11];
    const float* W_V   = (const float*)d_in[12];
    const float* cW1   = (const float*)d_in[13];
    const float* cb1   = (const float*)d_in[14];
    const float* cW2   = (const float*)d_in[15];
    const float* cb2   = (const float*)d_in[16];
    float* out = (float*)d_out;

    cudaFuncSetAttribute(k_mlp_single, cudaFuncAttributeMaxDynamicSharedMemorySize, SMEM_MLP);
    cudaFuncSetAttribute(k_mlp_dual,   cudaFuncAttributeMaxDynamicSharedMemorySize, SMEM_MLP);

    float *pQall, *pWkv, *pAttnA, *pQkv, *pAo, *pY, *pKV, *pS, *pDz, *pE;
    cudaGetSymbolAddress((void**)&pQall, g_qall);
    cudaGetSymbolAddress((void**)&pWkv, g_Wkv);
    cudaGetSymbolAddress((void**)&pAttnA, g_attnA);
    cudaGetSymbolAddress((void**)&pQkv, g_qkv);
    cudaGetSymbolAddress((void**)&pAo, g_ao);
    cudaGetSymbolAddress((void**)&pY, g_y);
    cudaGetSymbolAddress((void**)&pKV, g_kv);
    cudaGetSymbolAddress((void**)&pS, g_s);
    cudaGetSymbolAddress((void**)&pDz, g_dz);
    cudaGetSymbolAddress((void**)&pE, g_e);

    k_init<<<((long)BB*DD*HM + 255)/256, 256>>>(mW1, mb1, mW2, mb2, W_K, W_V);
    k_prepack<<<((long)NSEG*BB*(PP+CC)*DD + 255)/256, 256>>>(x, pers);

    // Q_all = x @ W_Q  (M = 32768)
    t_gemm<false,false><<<dim3(DD/64, (BB*SS)/64, 1), 256>>>(
        x, W_Q, nullptr, pQall, BB*SS, DD, DD, DD, DD, DD, 0L, 0L, 0L, 0);

    // h(0) = silu(q(0) @ W1 + b1) @ W2 + b2
    k_mlp_single<<<dim3(1, CC/64, BB), 256, SMEM_MLP>>>(
        0, pQall, pAttnA + PP*DD, nullptr, nullptr, nullptr,
        CC, DD, (long)SS*DD, (long)LL*DD);

    for (int s = 0; s < NSEG; s++) {
        int s0 = s * CC;
        float* pAttnS = pAttnA + (long)s*BB*LL*DD;

        // qkv = attn_in @ in_proj_w^T + in_proj_b  (M = 4224)
        t_gemm<true,true><<<dim3((3*DD)/64, (BB*LL)/64, 1), 256>>>(
            pAttnS, in_w, in_b, pQkv, BB*LL, 3*DD, DD, DD, DD, 3*DD, 0L, 0L, 0L, 0);
        k_attn2<<<BB*NH*(LL/8), 256>>>();
        // y = ao @ out_proj_w^T + out_proj_b
        t_gemm<true,true><<<dim3(DD/64, (BB*LL)/64, 1), 256>>>(
            pAo, out_w, out_b, pY, BB*LL, DD, DD, DD, DD, DD, 0L, 0L, 0L, 0);
        k_coef<<<BB, 256>>>(cW1, cb1, cW2, cb2);
        // [k|v] = y @ Wkv
        t_gemm<false,false><<<dim3((2*DD)/64, (BB*LL)/64, 1), 256>>>(
            pY, pWkv, nullptr, pKV, BB*LL, 2*DD, DD, DD, 2*DD, 2*DD, 0L, 0L, 0L, 0);

        // fused grad: z, s, e, dz
        k_mlp_single<<<dim3(1, (LL+63)/64, BB), 256, SMEM_MLP>>>(
            1, pKV, pS, pE, pDz, pKV + DD,
            LL, 2*DD, (long)LL*2*DD, (long)LL*HM);

        // gW2+gb2 and gW1+gb1 in ONE launch (independent halves overlap)
        k_grad<<<dim3(4, 4, 2*BB), 256>>>();

        k_update<<<((long)BB*PER + 255)/256, 256>>>();

        if (s < NSEG-1) {
            // fused: out(s) = y_last * mem_apply(y_last)  AND  h(s+1)
            k_mlp_dual<<<dim3(1, CC/64, 2*BB), 256, SMEM_MLP>>>(
                pY + (long)(PP+CC)*DD, out + (long)s0*DD,
                pQall + (long)(s0+CC)*DD, pAttnA + (long)(s+1)*BB*LL*DD + PP*DD,
                (long)LL*DD, (long)SS*DD, (long)SS*DD, (long)LL*DD);
        } else {
            k_mlp_single<<<dim3(1, CC/64, BB), 256, SMEM_MLP>>>(
                2, pY + (long)(PP+CC)*DD, out + (long)s0*DD, nullptr, nullptr, nullptr,
                CC, DD, (long)LL*DD, (long)SS*DD);
        }
    }
}

// round 13
// speedup vs baseline: 1.5013x; 1.1603x over previous
#include <cuda_runtime.h>
#include <cuda_bf16.h>
#include <math.h>

#define BB 16
#define SS 2048
#define DD 256
#define HM 256
#define PP 8
#define CHN 16
#define CC 128
#define LL 264            // PP + 2*CC
#define NH 8
#define HD 32
#define NSEG 16
#define LD_INV (1.0f/((float)LL*(float)DD))

#define MROWS 32          // MLP kernel M-tile
#define APITCH 264        // A/H smem pitch (bf16 elems)
#define BPITCH 26         // B stage pitch (bf16 elems)
#define SMEM_MLP (4*MROWS*APITCH*2 + 2*2*256*BPITCH*2 + 2*256*4)

// ---------------- persistent scratch (device globals; no allocation) -------
__device__ __align__(16) float g_fastW1[BB*DD*HM];
__device__ __align__(16) float g_fastb1[BB*HM];
__device__ __align__(16) float g_fastW2[BB*HM*DD];
__device__ __align__(16) float g_fastb2[BB*DD];
__device__ __align__(16) float g_momW1[BB*DD*HM];
__device__ __align__(16) float g_momb1[BB*HM];
__device__ __align__(16) float g_momW2[BB*HM*DD];
__device__ __align__(16) float g_momb2[BB*DD];
__device__ __align__(16) float g_qall[BB*SS*DD];
__device__ __align__(16) float g_Wkv[DD*2*DD];
__device__ __align__(16) float g_attnA[NSEG*BB*LL*DD];
__device__ __align__(16) float g_qkv[BB*LL*3*DD];
__device__ __align__(16) float g_ao[BB*LL*DD];
__device__ __align__(16) float g_y[BB*LL*DD];
__device__ __align__(16) float g_kv[BB*LL*2*DD];
__device__ __align__(16) float g_s[BB*LL*HM];
__device__ __align__(16) float g_dz[BB*LL*HM];
__device__ __align__(16) float g_e[BB*LL*DD];
__device__ float g_coef[BB*3];

// ---------------- bf16 split helpers (truncation hi + rn lo) ---------------
__device__ __forceinline__ void split2(float x0, float x1, unsigned& ph, unsigned& pl) {
    unsigned b0 = __float_as_uint(x0), b1 = __float_as_uint(x1);
    ph = __byte_perm(b0, b1, 0x7632);
    float l0 = x0 - __uint_as_float(b0 & 0xFFFF0000u);
    float l1 = x1 - __uint_as_float(b1 & 0xFFFF0000u);
    __nv_bfloat162 t = __float22bfloat162_rn(make_float2(l0, l1));
    pl = *(unsigned*)&t;
}
__device__ __forceinline__ void split1(float x, __nv_bfloat16& h, __nv_bfloat16& l) {
    unsigned b = __float_as_uint(x);
    unsigned short hs = (unsigned short)(b >> 16);
    h = *reinterpret_cast<__nv_bfloat16*>(&hs);
    l = __float2bfloat16(x - __uint_as_float(b & 0xFFFF0000u));
}
#define MMA_BF16(d, a, bq) \
    asm volatile("mma.sync.aligned.m16n8k16.row.col.f32.bf16.bf16.f32 " \
        "{%0,%1,%2,%3}, {%4,%5,%6,%7}, {%8,%9}, {%0,%1,%2,%3};" \
        : "+f"(d[0]), "+f"(d[1]), "+f"(d[2]), "+f"(d[3]) \
        : "r"(a[0]), "r"(a[1]), "r"(a[2]), "r"(a[3]), "r"(bq[0]), "r"(bq[1]))

// ---------------- init: fast weights, momentum, Wkv concat -----------------
__global__ void k_init(const float* __restrict__ mW1, const float* __restrict__ mb1,
                       const float* __restrict__ mW2, const float* __restrict__ mb2,
                       const float* __restrict__ W_K, const float* __restrict__ W_V) {
    long i = (long)blockIdx.x * blockDim.x + threadIdx.x;
    if (i < (long)BB*DD*HM) {
        g_fastW1[i] = mW1[i % (DD*HM)]; g_momW1[i] = 0.f;
        g_fastW2[i] = mW2[i % (HM*DD)]; g_momW2[i] = 0.f;
    }
    if (i < BB*HM) { g_fastb1[i] = mb1[i % HM]; g_momb1[i] = 0.f; }
    if (i < BB*DD) { g_fastb2[i] = mb2[i % DD]; g_momb2[i] = 0.f; }
    if (i < DD*2*DD) {
        int k = (int)(i >> 9), n = (int)(i & 511);
        g_Wkv[i] = (n < DD) ? W_K[k*DD + n] : W_V[k*DD + n - DD];
    }
}

// ---------------- prepack pers + x slices for ALL segments -----------------
__global__ void k_prepack(const float* __restrict__ x, const float* __restrict__ pers) {
    long i = (long)blockIdx.x * blockDim.x + threadIdx.x;
    const long TOT = (long)NSEG*BB*(PP+CC)*DD;
    if (i >= TOT) return;
    int d = (int)(i % DD);
    long t1 = i / DD;
    int t = (int)(t1 % (PP+CC));
    long t2 = t1 / (PP+CC);
    int b = (int)(t2 % BB);
    int s = (int)(t2 / BB);
    int row = (t < PP) ? t : (t + CC);
    float v = (t < PP) ? pers[t*DD + d]
                       : x[(long)b*SS*DD + (long)(s*CC + t - PP)*DD + d];
    g_attnA[(((long)s*BB + b)*LL + row)*DD + d] = v;
}

// ---------------- fused memory-MLP body (32-row tiles) ---------------------
// mode 0: O1 = silu(A@W1+b1)@W2+b2
// mode 1: z=A@W1+b1; s=silu(z)->O1; e=(s@W2+b2-v)*LD_INV->O2; dz=(e@W2^T)*silu'(z)->O3
// mode 2: O1 = (silu(A@W1+b1)@W2+b2) * A
__device__ __forceinline__ void mlp_body(
    int mode, const float* Ain, float* O1, float* O2, float* O3,
    const float* Vin, int b, int m0, int M, int lda, long sA, long sO1)
{
    extern __shared__ __align__(16) char smraw[];
    __nv_bfloat16* Ah  = (__nv_bfloat16*)smraw;
    __nv_bfloat16* Al  = Ah + MROWS*APITCH;
    __nv_bfloat16* Hh  = Al + MROWS*APITCH;
    __nv_bfloat16* Hl  = Hh + MROWS*APITCH;
    __nv_bfloat16* BsH = Hl + MROWS*APITCH;         // [2][256][BPITCH]
    __nv_bfloat16* BsL = BsH + 2*256*BPITCH;
    float* biasS = (float*)(BsL + 2*256*BPITCH);    // [2][256]

    int tid = threadIdx.x;
    const float* W1 = g_fastW1 + (long)b*DD*HM;
    const float* W2 = g_fastW2 + (long)b*HM*DD;
    Ain += (long)b * sA;
    O1  += (long)b * sO1;
    if (mode == 1) {
        O2  += (long)b * (long)LL*DD;
        O3  += (long)b * (long)LL*HM;
        Vin += (long)b * (long)LL*2*DD;
    }

    biasS[tid]       = g_fastb1[b*HM + tid];
    biasS[256 + tid] = g_fastb2[b*DD + tid];

    // stage A (32 x 256) split into Ah/Al
    #pragma unroll
    for (int j = 0; j < 8; j++) {
        int f = tid + j*256;
        int r = f >> 6, c4 = (f & 63) * 4;
        int rr = m0 + r; if (rr >= M) rr = M - 1;
        float4 v = *(const float4*)(Ain + (long)rr*lda + c4);
        unsigned ph0, pl0, ph1, pl1;
        split2(v.x, v.y, ph0, pl0); split2(v.z, v.w, ph1, pl1);
        *(unsigned*)&Ah[r*APITCH + c4]     = ph0;
        *(unsigned*)&Ah[r*APITCH + c4 + 2] = ph1;
        *(unsigned*)&Al[r*APITCH + c4]     = pl0;
        *(unsigned*)&Al[r*APITCH + c4 + 2] = pl1;
    }
    __syncthreads();

    int warp = tid >> 5, lane = tid & 31;
    int wn = warp;                         // 8 warps x 32 cols, full 32 rows
    int g = lane >> 2, tq = lane & 3;
    float acc[2][4][4];
    float vv0[16], vv1[16];

    auto loadB = [&](const float* W, int ldw, int tb, int kt, float* vv) {
        if (tb) {
            const float* p = W + (long)tid*ldw + kt*16;
            #pragma unroll
            for (int j = 0; j < 4; j++) {
                float4 t4 = *(const float4*)(p + j*4);
                vv[j*4]=t4.x; vv[j*4+1]=t4.y; vv[j*4+2]=t4.z; vv[j*4+3]=t4.w;
            }
        } else {
            const float* p = W + (long)(kt*16)*ldw + tid;
            #pragma unroll
            for (int k = 0; k < 16; k++) vv[k] = p[(long)k*ldw];
        }
    };
    auto storeB = [&](int buf, const float* vv) {
        __nv_bfloat16* dh = BsH + (buf*256 + tid)*BPITCH;
        __nv_bfloat16* dl = BsL + (buf*256 + tid)*BPITCH;
        #pragma unroll
        for (int k = 0; k < 16; k += 2) {
            unsigned ph, pl;
            split2(vv[k], vv[k+1], ph, pl);
            *(unsigned*)&dh[k] = ph;
            *(unsigned*)&dl[k] = pl;
        }
    };
    auto mma_tile = [&](const __nv_bfloat16* Xh, const __nv_bfloat16* Xl, int kt) {
        int cur = kt & 1;
        int ko = kt*16 + tq*2;
        unsigned ah[2][4], al[2][4];
        #pragma unroll
        for (int mi = 0; mi < 2; mi++) {
            int r = mi*16 + g;
            ah[mi][0] = *(const unsigned*)&Xh[r*APITCH + ko];
            ah[mi][1] = *(const unsigned*)&Xh[(r+8)*APITCH + ko];
            ah[mi][2] = *(const unsigned*)&Xh[r*APITCH + ko + 8];
            ah[mi][3] = *(const unsigned*)&Xh[(r+8)*APITCH + ko + 8];
            al[mi][0] = *(const unsigned*)&Xl[r*APITCH + ko];
            al[mi][1] = *(const unsigned*)&Xl[(r+8)*APITCH + ko];
            al[mi][2] = *(const unsigned*)&Xl[r*APITCH + ko + 8];
            al[mi][3] = *(const unsigned*)&Xl[(r+8)*APITCH + ko + 8];
        }
        #pragma unroll
        for (int ni = 0; ni < 4; ni++) {
            int nr = wn*32 + ni*8 + g;
            const __nv_bfloat16* ph = BsH + (cur*256 + nr)*BPITCH + tq*2;
            const __nv_bfloat16* pl = BsL + (cur*256 + nr)*BPITCH + tq*2;
            unsigned bh[2], bl[2];
            bh[0] = *(const unsigned*)ph; bh[1] = *(const unsigned*)(ph + 8);
            bl[0] = *(const unsigned*)pl; bl[1] = *(const unsigned*)(pl + 8);
            #pragma unroll
            for (int mi = 0; mi < 2; mi++) {
                MMA_BF16(acc[mi][ni], ah[mi], bh);
                MMA_BF16(acc[mi][ni], al[mi], bh);
                MMA_BF16(acc[mi][ni], ah[mi], bl);
            }
        }
    };
    auto run_gemm = [&](const __nv_bfloat16* Xh, const __nv_bfloat16* Xl,
                        const float* W, int ldw, int tb) {
        #pragma unroll
        for (int mi = 0; mi < 2; mi++)
            #pragma unroll
            for (int ni = 0; ni < 4; ni++)
                #pragma unroll
                for (int e = 0; e < 4; e++) acc[mi][ni][e] = 0.f;
        loadB(W, ldw, tb, 0, vv0);
        storeB(0, vv0);
        loadB(W, ldw, tb, 1, vv1);
        __syncthreads();
        int kt = 0;
        while (true) {
            if (kt + 2 < 16) loadB(W, ldw, tb, kt + 2, vv0);
            mma_tile(Xh, Xl, kt);
            if (kt + 1 < 16) storeB((kt + 1) & 1, vv1);
            __syncthreads();
            if (++kt >= 16) break;
            if (kt + 2 < 16) loadB(W, ldw, tb, kt + 2, vv1);
            mma_tile(Xh, Xl, kt);
            if (kt + 1 < 16) storeB((kt + 1) & 1, vv0);
            __syncthreads();
            if (++kt >= 16) break;
        }
    };

    // ---- GEMM1: z = A @ W1 + b1 ; h1/s = silu(z) -> H buffers ----
    run_gemm(Ah, Al, W1, HM, 0);
    #pragma unroll
    for (int mi = 0; mi < 2; mi++)
    #pragma unroll
    for (int ni = 0; ni < 4; ni++)
    #pragma unroll
    for (int h2 = 0; h2 < 2; h2++) {
        int rl = mi*16 + g + h2*8;
        int c  = wn*32 + ni*8 + tq*2;
        float z0 = acc[mi][ni][h2*2+0] + biasS[c];
        float z1 = acc[mi][ni][h2*2+1] + biasS[c+1];
        float s0v = z0 / (1.f + expf(-z0));
        float s1v = z1 / (1.f + expf(-z1));
        unsigned ph, pl;
        split2(s0v, s1v, ph, pl);
        *(unsigned*)&Hh[rl*APITCH + c] = ph;
        *(unsigned*)&Hl[rl*APITCH + c] = pl;
        if (mode == 1) {
            split2(z0, z1, ph, pl);              // keep z (A is dead)
            *(unsigned*)&Ah[rl*APITCH + c] = ph;
            *(unsigned*)&Al[rl*APITCH + c] = pl;
            if (m0 + rl < M)
                *(float2*)&O1[(long)(m0+rl)*256 + c] = make_float2(s0v, s1v);
        }
    }
    __syncthreads();

    // ---- GEMM2: pred = s @ W2 + b2 ----
    run_gemm(Hh, Hl, W2, DD, 0);
    #pragma unroll
    for (int mi = 0; mi < 2; mi++)
    #pragma unroll
    for (int ni = 0; ni < 4; ni++)
    #pragma unroll
    for (int h2 = 0; h2 < 2; h2++) {
        int rl = mi*16 + g + h2*8;
        int c  = wn*32 + ni*8 + tq*2;
        float v0 = acc[mi][ni][h2*2+0] + biasS[256 + c];
        float v1 = acc[mi][ni][h2*2+1] + biasS[256 + c + 1];
        bool valid = (m0 + rl) < M;
        long ro = (long)(m0 + rl) * 256 + c;
        if (mode == 0) {
            if (valid) *(float2*)&O1[ro] = make_float2(v0, v1);
        } else if (mode == 2) {
            float y0 = __bfloat162float(Ah[rl*APITCH + c])   + __bfloat162float(Al[rl*APITCH + c]);
            float y1 = __bfloat162float(Ah[rl*APITCH + c+1]) + __bfloat162float(Al[rl*APITCH + c+1]);
            if (valid) *(float2*)&O1[ro] = make_float2(v0*y0, v1*y1);
        } else {
            float e0 = 0.f, e1 = 0.f;
            if (valid) {
                float2 vr = *(const float2*)&Vin[(long)(m0+rl)*(2*DD) + c];
                e0 = (v0 - vr.x) * LD_INV;
                e1 = (v1 - vr.y) * LD_INV;
                *(float2*)&O2[ro] = make_float2(e0, e1);
            }
            unsigned ph, pl;
            split2(e0, e1, ph, pl);              // e -> H buffers (s is dead)
            *(unsigned*)&Hh[rl*APITCH + c] = ph;
            *(unsigned*)&Hl[rl*APITCH + c] = pl;
        }
    }

    // ---- GEMM3 (mode 1): dz = (e @ W2^T) * silu'(z) ----
    if (mode == 1) {
        __syncthreads();
        run_gemm(Hh, Hl, W2, DD, 1);
        #pragma unroll
        for (int mi = 0; mi < 2; mi++)
        #pragma unroll
        for (int ni = 0; ni < 4; ni++)
        #pragma unroll
        for (int h2 = 0; h2 < 2; h2++) {
            int rl = mi*16 + g + h2*8;
            int c  = wn*32 + ni*8 + tq*2;
            if (m0 + rl < M) {
                float z0 = __bfloat162float(Ah[rl*APITCH + c])   + __bfloat162float(Al[rl*APITCH + c]);
                float z1 = __bfloat162float(Ah[rl*APITCH + c+1]) + __bfloat162float(Al[rl*APITCH + c+1]);
                float sg0 = 1.f/(1.f+expf(-z0)), sg1 = 1.f/(1.f+expf(-z1));
                float d0 = acc[mi][ni][h2*2+0] * sg0 * (1.f + z0*(1.f - sg0));
                float d1 = acc[mi][ni][h2*2+1] * sg1 * (1.f + z1*(1.f - sg1));
                *(float2*)&O3[(long)(m0+rl)*256 + c] = make_float2(d0, d1);
            }
        }
    }
}

__global__ __launch_bounds__(256) void k_mlp_single(
    int mode, const float* Ain, float* O1, float* O2, float* O3,
    const float* Vin, int M, int lda, long sA, long sO1)
{
    mlp_body(mode, Ain, O1, O2, O3, Vin, blockIdx.z, blockIdx.y*MROWS, M, lda, sA, sO1);
}

// dual launch: z<BB -> mode2 (gated out, seg s); z>=BB -> mode0 (h, seg s+1)
__global__ __launch_bounds__(256) void k_mlp_dual(
    const float* A2, float* O2out, const float* A0, float* O0out,
    long sA2, long sO2, long sA0, long sO0)
{
    int z = blockIdx.z;
    if (z < BB) mlp_body(2, A2, O2out, nullptr, nullptr, nullptr, z,      blockIdx.y*MROWS, CC, DD, sA2, sO2);
    else        mlp_body(0, A0, O0out, nullptr, nullptr, nullptr, z - BB, blockIdx.y*MROWS, CC, DD, sA0, sO0);
}

#define KP 24

// ---------------- tensor-core GEMM (bf16x3), 64x64 tile, pipelined ---------
// A is [M][K].  TB: B is [N][K]; else [K][N].  K % 16 == 0, K >= 32.
template<bool TB, bool BIAS>
__global__ __launch_bounds__(256) void t_gemm(
        const float* __restrict__ A, const float* __restrict__ Bw,
        const float* __restrict__ bias, float* __restrict__ C,
        int M, int N, int K, int lda, int ldb, int ldc,
        long sA, long sB, long sC, int sBias) {
    __shared__ __align__(16) __nv_bfloat16 AsH[2][64][KP];
    __shared__ __align__(16) __nv_bfloat16 AsL[2][64][KP];
    __shared__ __align__(16) __nv_bfloat16 BsH[2][64][KP];
    __shared__ __align__(16) __nv_bfloat16 BsL[2][64][KP];
    int b = blockIdx.z;
    A  += (long)b * sA;
    Bw += (long)b * sB;
    C  += (long)b * sC;
    if (BIAS) bias += (long)b * sBias;
    int tid = threadIdx.x;
    int n0 = blockIdx.x * 64, m0 = blockIdx.y * 64;
    int nkt = K >> 4;

    int am  = tid >> 2, akq = (tid & 3) * 4;
    int bkr = tid >> 4, bnq = (tid & 15) * 4;
    int bn  = tid >> 2, bkq = (tid & 3) * 4;

    int r0 = m0 + am; if (r0 >= M) r0 = M - 1;
    const float* Aptr = A + (long)r0*lda;

    auto readAr = [&](int kt, float* ar) {
        float4 v = *(const float4*)(Aptr + kt*16 + akq);
        ar[0]=v.x; ar[1]=v.y; ar[2]=v.z; ar[3]=v.w;
    };
    auto readBr = [&](int kt, float* br) {
        if (!TB) {
            float4 v = *(const float4*)(Bw + (long)(kt*16 + bkr)*ldb + n0 + bnq);
            br[0]=v.x; br[1]=v.y; br[2]=v.z; br[3]=v.w;
        } else {
            float4 v = *(const float4*)(Bw + (long)(n0+bn)*ldb + kt*16 + bkq);
            br[0]=v.x; br[1]=v.y; br[2]=v.z; br[3]=v.w;
        }
    };
    auto storeAr = [&](int buf, const float* ar) {
        unsigned ph0, pl0, ph1, pl1;
        split2(ar[0], ar[1], ph0, pl0);
        split2(ar[2], ar[3], ph1, pl1);
        *(unsigned*)&AsH[buf][am][akq]   = ph0;
        *(unsigned*)&AsH[buf][am][akq+2] = ph1;
        *(unsigned*)&AsL[buf][am][akq]   = pl0;
        *(unsigned*)&AsL[buf][am][akq+2] = pl1;
    };
    auto storeBr = [&](int buf, const float* br) {
        if (!TB) {
            #pragma unroll
            for (int j = 0; j < 4; j++) {
                __nv_bfloat16 h, l;
                split1(br[j], h, l);
                BsH[buf][bnq+j][bkr] = h;
                BsL[buf][bnq+j][bkr] = l;
            }
        } else {
            unsigned ph0, pl0, ph1, pl1;
            split2(br[0], br[1], ph0, pl0);
            split2(br[2], br[3], ph1, pl1);
            *(unsigned*)&BsH[buf][bn][bkq]   = ph0;
            *(unsigned*)&BsH[buf][bn][bkq+2] = ph1;
            *(unsigned*)&BsL[buf][bn][bkq]   = pl0;
            *(unsigned*)&BsL[buf][bn][bkq+2] = pl1;
        }
    };

    int warp = tid >> 5, lane = tid & 31;
    int wm = warp & 1, wn = warp >> 1;
    int g = lane >> 2, tq = lane & 3;
    int ko = tq * 2;
    float acc[2][2][4] = {};

    auto mma_on = [&](int cur) {
        unsigned ah[2][4], al[2][4], bh[2][2], bl[2][2];
        #pragma unroll
        for (int mi = 0; mi < 2; mi++) {
            int r = wm*32 + mi*16 + g;
            ah[mi][0] = *(const unsigned*)&AsH[cur][r][ko];
            ah[mi][1] = *(const unsigned*)&AsH[cur][r+8][ko];
            ah[mi][2] = *(const unsigned*)&AsH[cur][r][ko+8];
            ah[mi][3] = *(const unsigned*)&AsH[cur][r+8][ko+8];
            al[mi][0] = *(const unsigned*)&AsL[cur][r][ko];
            al[mi][1] = *(const unsigned*)&AsL[cur][r+8][ko];
            al[mi][2] = *(const unsigned*)&AsL[cur][r][ko+8];
            al[mi][3] = *(const unsigned*)&AsL[cur][r+8][ko+8];
        }
        #pragma unroll
        for (int ni = 0; ni < 2; ni++) {
            int nr = wn*16 + ni*8 + g;
            bh[ni][0] = *(const unsigned*)&BsH[cur][nr][ko];
            bh[ni][1] = *(const unsigned*)&BsH[cur][nr][ko+8];
            bl[ni][0] = *(const unsigned*)&BsL[cur][nr][ko];
            bl[ni][1] = *(const unsigned*)&BsL[cur][nr][ko+8];
        }
        #pragma unroll
        for (int mi = 0; mi < 2; mi++)
            #pragma unroll
            for (int ni = 0; ni < 2; ni++) {
                MMA_BF16(acc[mi][ni], ah[mi], bh[ni]);
                MMA_BF16(acc[mi][ni], al[mi], bh[ni]);
                MMA_BF16(acc[mi][ni], ah[mi], bl[ni]);
            }
    };

    float a0[4], b0r[4], a1[4], b1r[4];
    readAr(0, a0); readBr(0, b0r);
    storeAr(0, a0); storeBr(0, b0r);
    readAr(1, a1); readBr(1, b1r);
    __syncthreads();
    int kt = 0;
    while (true) {
        if (kt + 2 < nkt) { readAr(kt+2, a0); readBr(kt+2, b0r); }
        mma_on(kt & 1);
        if (kt + 1 < nkt) { storeAr((kt+1) & 1, a1); storeBr((kt+1) & 1, b1r); }
        __syncthreads();
        if (++kt >= nkt) break;
        if (kt + 2 < nkt) { readAr(kt+2, a1); readBr(kt+2, b1r); }
        mma_on(kt & 1);
        if (kt + 1 < nkt) { storeAr((kt+1) & 1, a0); storeBr((kt+1) & 1, b0r); }
        __syncthreads();
        if (++kt >= nkt) break;
    }

    #pragma unroll
    for (int mi = 0; mi < 2; mi++) {
        #pragma unroll
        for (int ni = 0; ni < 2; ni++) {
            int c0 = n0 + wn*16 + ni*8 + tq*2;
            float bv0 = 0.f, bv1 = 0.f;
            if (BIAS) { bv0 = bias[c0]; bv1 = bias[c0+1]; }
            #pragma unroll
            for (int h2 = 0; h2 < 2; h2++) {
                int r = m0 + wm*32 + mi*16 + g + h2*8;
                if (r < M) {
                    C[(long)r*ldc + c0]   = acc[mi][ni][h2*2+0] + bv0;
                    C[(long)r*ldc + c0+1] = acc[mi][ni][h2*2+1] + bv1;
                }
            }
        }
    }
}

// ---------------- fused grad GEMM + momentum/decay update ------------------
// z<16: gW2 tile = s^T e, update fastW2/momW2 (+b2 via colsum e)
// z>=16: gW1 tile = k^T dz, update fastW1/momW1 (+b1 via colsum dz)
__global__ __launch_bounds__(256) void k_grad() {
    __shared__ __align__(16) __nv_bfloat16 AsH[2][64][KP];
    __shared__ __align__(16) __nv_bfloat16 AsL[2][64][KP];
    __shared__ __align__(16) __nv_bfloat16 BsH[2][64][KP];
    __shared__ __align__(16) __nv_bfloat16 BsL[2][64][KP];
    int z = blockIdx.z;
    int b = z & (BB-1);
    bool sel = z >= BB;
    const float *A, *B;
    float *fp, *mp, *fbp, *mbp;
    int lda, ldb;
    if (!sel) {
        A = g_s  + (long)b*LL*HM;   B = g_e  + (long)b*LL*DD;
        fp = g_fastW2 + (long)b*HM*DD; mp = g_momW2 + (long)b*HM*DD;
        fbp = g_fastb2 + b*DD; mbp = g_momb2 + b*DD;
        lda = HM;   ldb = DD;
    } else {
        A = g_kv + (long)b*LL*2*DD; B = g_dz + (long)b*LL*HM;
        fp = g_fastW1 + (long)b*DD*HM; mp = g_momW1 + (long)b*DD*HM;
        fbp = g_fastb1 + b*HM; mbp = g_momb1 + b*HM;
        lda = 2*DD; ldb = HM;
    }
    const int K = LL, nkt = 17;
    int tid = threadIdx.x;
    int n0 = blockIdx.x * 64, m0 = blockIdx.y * 64;

    int akr = tid >> 4, amq = (tid & 15) * 4;
    int bkr = tid >> 4, bnq = (tid & 15) * 4;

    auto readAr = [&](int kt, float* ar) {
        int kr = kt*16 + akr;
        if (kr < K) {
            float4 v = *(const float4*)(A + (long)kr*lda + m0 + amq);
            ar[0]=v.x; ar[1]=v.y; ar[2]=v.z; ar[3]=v.w;
        } else { ar[0]=ar[1]=ar[2]=ar[3]=0.f; }
    };
    auto readBr = [&](int kt, float* br) {
        int kr = kt*16 + bkr;
        if (kr < K) {
            float4 v = *(const float4*)(B + (long)kr*ldb + n0 + bnq);
            br[0]=v.x; br[1]=v.y; br[2]=v.z; br[3]=v.w;
        } else { br[0]=br[1]=br[2]=br[3]=0.f; }
    };
    auto storeAr = [&](int buf, const float* ar) {
        #pragma unroll
        for (int j = 0; j < 4; j++) {
            __nv_bfloat16 h, l;
            split1(ar[j], h, l);
            AsH[buf][amq+j][akr] = h;
            AsL[buf][amq+j][akr] = l;
        }
    };
    auto storeBr = [&](int buf, const float* br) {
        #pragma unroll
        for (int j = 0; j < 4; j++) {
            __nv_bfloat16 h, l;
            split1(br[j], h, l);
            BsH[buf][bnq+j][bkr] = h;
            BsL[buf][bnq+j][bkr] = l;
        }
    };

    int warp = tid >> 5, lane = tid & 31;
    int wm = warp & 1, wn = warp >> 1;
    int g = lane >> 2, tq = lane & 3;
    int ko = tq * 2;
    float acc[2][2][4] = {};
    float csum = 0.f;

    auto mma_on = [&](int cur) {
        unsigned ah[2][4], al[2][4], bh[2][2], bl[2][2];
        #pragma unroll
        for (int mi = 0; mi < 2; mi++) {
            int r = wm*32 + mi*16 + g;
            ah[mi][0] = *(const unsigned*)&AsH[cur][r][ko];
            ah[mi][1] = *(const unsigned*)&AsH[cur][r+8][ko];
            ah[mi][2] = *(const unsigned*)&AsH[cur][r][ko+8];
            ah[mi][3] = *(const unsigned*)&AsH[cur][r+8][ko+8];
            al[mi][0] = *(const unsigned*)&AsL[cur][r][ko];
            al[mi][1] = *(const unsigned*)&AsL[cur][r+8][ko];
            al[mi][2] = *(const unsigned*)&AsL[cur][r][ko+8];
            al[mi][3] = *(const unsigned*)&AsL[cur][r+8][ko+8];
        }
        #pragma unroll
        for (int ni = 0; ni < 2; ni++) {
            int nr = wn*16 + ni*8 + g;
            bh[ni][0] = *(const unsigned*)&BsH[cur][nr][ko];
            bh[ni][1] = *(const unsigned*)&BsH[cur][nr][ko+8];
            bl[ni][0] = *(const unsigned*)&BsL[cur][nr][ko];
            bl[ni][1] = *(const unsigned*)&BsL[cur][nr][ko+8];
        }
        if (tid < 64) {
            #pragma unroll
            for (int k2 = 0; k2 < 16; k2 += 2) {
                float2 hf = __bfloat1622float2(*(const __nv_bfloat162*)&BsH[cur][tid][k2]);
                float2 lf = __bfloat1622float2(*(const __nv_bfloat162*)&BsL[cur][tid][k2]);
                csum += hf.x + hf.y + lf.x + lf.y;
            }
        }
        #pragma unroll
        for (int mi = 0; mi < 2; mi++)
            #pragma unroll
            for (int ni = 0; ni < 2; ni++) {
                MMA_BF16(acc[mi][ni], ah[mi], bh[ni]);
                MMA_BF16(acc[mi][ni], al[mi], bh[ni]);
                MMA_BF16(acc[mi][ni], ah[mi], bl[ni]);
            }
    };

    float a0[4], b0r[4], a1[4], b1r[4];
    readAr(0, a0); readBr(0, b0r);
    storeAr(0, a0); storeBr(0, b0r);
    readAr(1, a1); readBr(1, b1r);
    __syncthreads();
    int kt = 0;
    while (true) {
        if (kt + 2 < nkt) { readAr(kt+2, a0); readBr(kt+2, b0r); }
        mma_on(kt & 1);
        if (kt + 1 < nkt) { storeAr((kt+1) & 1, a1); storeBr((kt+1) & 1, b1r); }
        __syncthreads();
        if (++kt >= nkt) break;
        if (kt + 2 < nkt) { readAr(kt+2, a1); readBr(kt+2, b1r); }
        mma_on(kt & 1);
        if (kt + 1 < nkt) { storeAr((kt+1) & 1, a0); storeBr((kt+1) & 1, b0r); }
        __syncthreads();
        if (++kt >= nkt) break;
    }

    float alpha = g_coef[b*3+0], eta = g_coef[b*3+1], theta = g_coef[b*3+2];

    if (blockIdx.y == 0 && tid < 64) {
        int idx = n0 + tid;
        float m = eta * mbp[idx] - theta * csum;
        mbp[idx] = m;
        fbp[idx] = (1.f - alpha) * fbp[idx] + m;
    }

    #pragma unroll
    for (int mi = 0; mi < 2; mi++)
        #pragma unroll
        for (int ni = 0; ni < 2; ni++) {
            int c0 = n0 + wn*16 + ni*8 + tq*2;
            #pragma unroll
            for (int h2 = 0; h2 < 2; h2++) {
                int r = m0 + wm*32 + mi*16 + g + h2*8;
                long i0 = (long)r*256 + c0;
                float m0v = eta * mp[i0]   - theta * acc[mi][ni][h2*2+0];
                float m1v = eta * mp[i0+1] - theta * acc[mi][ni][h2*2+1];
                mp[i0]   = m0v;
                mp[i0+1] = m1v;
                fp[i0]   = (1.f - alpha) * fp[i0]   + m0v;
                fp[i0+1] = (1.f - alpha) * fp[i0+1] + m1v;
            }
        }
}

// ---------------- attention: block = (b, head, 8-row tile), smem K/V -------
__global__ void k_attn2() {
    __shared__ float Ks[64][33];
    __shared__ float Vs[64][33];
    __shared__ float qs[8][32];
    __shared__ float ps[8][32];
    int blk = blockIdx.x;
    int tile = blk % (LL/8);
    int hh = (blk / (LL/8)) % NH;
    int b  = blk / ((LL/8)*NH);
    int rt0 = tile * 8;
    int tid = threadIdx.x;
    int w = tid >> 5, lane = tid & 31;
    int r = rt0 + w;
    const float* base = g_qkv + (long)b*LL*3*DD;
    qs[w][lane] = base[(long)r*3*DD + hh*HD + lane] * 0.17677669529663687f;
    float m = -1e30f, l = 0.f, o = 0.f;
    int ntile = (rt0 + 71) >> 6;
    int krow = tid >> 3;
    int kc = (tid & 7) * 4;
    for (int jt = 0; jt < ntile; jt++) {
        int j0 = jt * 64;
        __syncthreads();
        #pragma unroll
        for (int half = 0; half < 2; half++) {
            int jl = krow + half*32;
            int jg = j0 + jl; if (jg > LL-1) jg = LL-1;
            const float* kp = base + (long)jg*3*DD + DD + hh*HD + kc;
            float4 k4 = *(const float4*)kp;
            float4 v4 = *(const float4*)(kp + DD);
            Ks[jl][kc]=k4.x; Ks[jl][kc+1]=k4.y; Ks[jl][kc+2]=k4.z; Ks[jl][kc+3]=k4.w;
            Vs[jl][kc]=v4.x; Vs[jl][kc+1]=v4.y; Vs[jl][kc+2]=v4.z; Vs[jl][kc+3]=v4.w;
        }
        __syncthreads();
        #pragma unroll
        for (int c = 0; c < 2; c++) {
            int jbase = j0 + c*32;
            if (jbase > r) break;
            int jl = c*32 + lane;
            int jg = jbase + lane;
            float sc = 0.f;
            #pragma unroll
            for (int d = 0; d < 32; d++) sc += qs[w][d] * Ks[jl][d];
            if (jg > r) sc = -1e30f;
            float cm = sc;
            #pragma unroll
            for (int s = 16; s; s >>= 1) cm = fmaxf(cm, __shfl_xor_sync(0xffffffffu, cm, s));
            float mn = fmaxf(m, cm);
            float p = (jg <= r) ? expf(sc - mn) : 0.f;
            __syncwarp();
            ps[w][lane] = p;
            float psum = p;
            #pragma unroll
            for (int s = 16; s; s >>= 1) psum += __shfl_xor_sync(0xffffffffu, psum, s);
            float corr = expf(m - mn);
            l = l*corr + psum; o *= corr; m = mn;
            __syncwarp();
            int jmax = min(32, r - jbase + 1);
            for (int jj = 0; jj < jmax; jj++)
                o += ps[w][jj] * Vs[c*32 + jj][lane];
        }
    }
    g_ao[((long)b*LL + r)*DD + hh*HD + lane] = o / l;
}

// ---------------- gate coefficients ----------------------------------------
__global__ void k_coef(const float* __restrict__ cW1, const float* __restrict__ cb1,
                       const float* __restrict__ cW2, const float* __restrict__ cb2) {
    int b = blockIdx.x, tid = threadIdx.x;
    __shared__ float ybar[DD];
    __shared__ float ch[CHN];
    float sum = 0.f;
    const float* yp = g_y + (long)b*LL*DD + tid;
    for (int t = 0; t < LL; t++) sum += yp[(long)t*DD];
    ybar[tid] = sum / (float)LL;
    __syncthreads();
    if (tid < CHN) {
        float a = cb1[tid];
        for (int d = 0; d < DD; d++) a += ybar[d] * cW1[d*CHN + tid];
        ch[tid] = a / (1.f + expf(-a));
    }
    __syncthreads();
    if (tid < 3) {
        float a = cb2[tid];
        for (int j = 0; j < CHN; j++) a += ch[j] * cW2[j*3 + tid];
        g_coef[b*3 + tid] = 1.f / (1.f + expf(-a));
    }
}

// ---------------------------------------------------------------------------
extern "C" void kernel_launch(void* const* d_in, const int* in_sizes, int n_in,
                              void* d_out, int out_size) {
    const float* x     = (const float*)d_in[0];
    const float* pers  = (const float*)d_in[1];
    const float* W_Q   = (const float*)d_in[2];
    const float* in_w  = (const float*)d_in[3];
    const float* in_b  = (const float*)d_in[4];
    const float* out_w = (const float*)d_in[5];
    const float* out_b = (const float*)d_in[6];
    const float* mW1   = (const float*)d_in[7];
    const float* mb1   = (const float*)d_in[8];
    const float* mW2   = (const float*)d_in[9];
    const float* mb2   = (const float*)d_in[10];
    const float* W_K   = (const float*)d_in[11];
    const float* W_V   = (const float*)d_in[12];
    const float* cW1   = (const float*)d_in[13];
    const float* cb1   = (const float*)d_in[14];
    const float* cW2   = (const float*)d_in[15];
    const float* cb2   = (const float*)d_in[16];
    float* out = (float*)d_out;

    cudaFuncSetAttribute(k_mlp_single, cudaFuncAttributeMaxDynamicSharedMemorySize, SMEM_MLP);
    cudaFuncSetAttribute(k_mlp_dual,   cudaFuncAttributeMaxDynamicSharedMemorySize, SMEM_MLP);

    float *pQall, *pWkv, *pAttnA, *pQkv, *pAo, *pY, *pKV, *pS, *pDz, *pE;
    cudaGetSymbolAddress((void**)&pQall, g_qall);
    cudaGetSymbolAddress((void**)&pWkv, g_Wkv);
    cudaGetSymbolAddress((void**)&pAttnA, g_attnA);
    cudaGetSymbolAddress((void**)&pQkv, g_qkv);
    cudaGetSymbolAddress((void**)&pAo, g_ao);
    cudaGetSymbolAddress((void**)&pY, g_y);
    cudaGetSymbolAddress((void**)&pKV, g_kv);
    cudaGetSymbolAddress((void**)&pS, g_s);
    cudaGetSymbolAddress((void**)&pDz, g_dz);
    cudaGetSymbolAddress((void**)&pE, g_e);

    k_init<<<((long)BB*DD*HM + 255)/256, 256>>>(mW1, mb1, mW2, mb2, W_K, W_V);
    k_prepack<<<((long)NSEG*BB*(PP+CC)*DD + 255)/256, 256>>>(x, pers);

    // Q_all = x @ W_Q  (M = 32768)
    t_gemm<false,false><<<dim3(DD/64, (BB*SS)/64, 1), 256>>>(
        x, W_Q, nullptr, pQall, BB*SS, DD, DD, DD, DD, DD, 0L, 0L, 0L, 0);

    // h(0) = silu(q(0) @ W1 + b1) @ W2 + b2
    k_mlp_single<<<dim3(1, CC/MROWS, BB), 256, SMEM_MLP>>>(
        0, pQall, pAttnA + PP*DD, nullptr, nullptr, nullptr,
        CC, DD, (long)SS*DD, (long)LL*DD);

    for (int s = 0; s < NSEG; s++) {
        int s0 = s * CC;
        float* pAttnS = pAttnA + (long)s*BB*LL*DD;

        // qkv = attn_in @ in_proj_w^T + in_proj_b  (M = 4224)
        t_gemm<true,true><<<dim3((3*DD)/64, (BB*LL)/64, 1), 256>>>(
            pAttnS, in_w, in_b, pQkv, BB*LL, 3*DD, DD, DD, DD, 3*DD, 0L, 0L, 0L, 0);
        k_attn2<<<BB*NH*(LL/8), 256>>>();
        // y = ao @ out_proj_w^T + out_proj_b
        t_gemm<true,true><<<dim3(DD/64, (BB*LL)/64, 1), 256>>>(
            pAo, out_w, out_b, pY, BB*LL, DD, DD, DD, DD, DD, 0L, 0L, 0L, 0);
        k_coef<<<BB, 256>>>(cW1, cb1, cW2, cb2);
        // [k|v] = y @ Wkv
        t_gemm<false,false><<<dim3((2*DD)/64, (BB*LL)/64, 1), 256>>>(
            pY, pWkv, nullptr, pKV, BB*LL, 2*DD, DD, DD, 2*DD, 2*DD, 0L, 0L, 0L, 0);

        // fused grad: z, s, e, dz   (9 x 16 = 144 blocks)
        k_mlp_single<<<dim3(1, (LL+MROWS-1)/MROWS, BB), 256, SMEM_MLP>>>(
            1, pKV, pS, pE, pDz, pKV + DD,
            LL, 2*DD, (long)LL*2*DD, (long)LL*HM);

        // gW2/gW1 tiles + fused momentum/decay weight update (one launch)
        k_grad<<<dim3(4, 4, 2*BB), 256>>>();

        if (s < NSEG-1) {
            // fused: out(s) = y_last * mem_apply(y_last)  AND  h(s+1)
            k_mlp_dual<<<dim3(1, CC/MROWS, 2*BB), 256, SMEM_MLP>>>(
                pY + (long)(PP+CC)*DD, out + (long)s0*DD,
                pQall + (long)(s0+CC)*DD, pAttnA + (long)(s+1)*BB*LL*DD + PP*DD,
                (long)LL*DD, (long)SS*DD, (long)SS*DD, (long)LL*DD);
        } else {
            k_mlp_single<<<dim3(1, CC/MROWS, BB), 256, SMEM_MLP>>>(
                2, pY + (long)(PP+CC)*DD, out + (long)s0*DD, nullptr, nullptr, nullptr,
                CC, DD, (long)LL*DD, (long)SS*DD);
        }
    }
}